// round 7
// baseline (speedup 1.0000x reference)
#include <cuda_runtime.h>

#define F     128
#define F4    32
#define NMAX  50000
#define EMAX  800000
#define TROW  64          // node rows per gemm block
#define PAD   132         // padded row length (floats) -> conflict-free fragments

// Scratch (allocation-free rule: __device__ globals)
__device__ __align__(16) float g_y[NMAX * F];      // tf32-rounded aggregated feats
__device__ __align__(16) float g_w1t[F * F];       // tf32-rounded W1
__device__ __align__(16) float g_w2t[F * F];       // tf32-rounded W2
__device__ __align__(16) float g_sum[F];
__device__ __align__(16) float g_sumsq[F];
__device__ int   g_cnt[NMAX];                      // histogram, then cursor
__device__ int   g_offs[NMAX + 1];                 // segment offsets
__device__ int   g_src_s[EMAX];                    // dst-sorted edge sources
__device__ float g_w_s[EMAX];                      // dst-sorted edge weights

// ---------------------------------------------------------------------------
__device__ __forceinline__ unsigned f2tf(float f) {
    unsigned u;
    asm("cvt.rna.tf32.f32 %0, %1;" : "=r"(u) : "f"(f));
    return u;
}
__device__ __forceinline__ float4 f2tf4(float4 v) {
    return make_float4(__uint_as_float(f2tf(v.x)), __uint_as_float(f2tf(v.y)),
                       __uint_as_float(f2tf(v.z)), __uint_as_float(f2tf(v.w)));
}

// Setup: zero counters/stats + one-time tf32 conversion of W1, W2
__global__ void setup_k(const float4* __restrict__ W1,
                        const float4* __restrict__ W2, int N) {
    int i = blockIdx.x * blockDim.x + threadIdx.x;
    if (i < N) g_cnt[i] = 0;
    if (i < F) { g_sum[i] = 0.0f; g_sumsq[i] = 0.0f; }
    if (i < F * F4) {
        ((float4*)g_w1t)[i] = f2tf4(W1[i]);
        ((float4*)g_w2t)[i] = f2tf4(W2[i]);
    }
}

__global__ void hist_k(const int* __restrict__ dst, int E) {
    for (int e = blockIdx.x * blockDim.x + threadIdx.x; e < E;
         e += gridDim.x * blockDim.x)
        atomicAdd(&g_cnt[dst[e]], 1);
}

// Single-block exclusive scan: 512 threads, sequential chunks
__global__ void scan_k(int N, int E) {
    __shared__ int sh[512];
    int t = threadIdx.x;
    int CH = (N + 511) >> 9;
    int base = t * CH;
    int lim = base + CH; if (lim > N) lim = N;
    int s = 0;
    for (int i = base; i < lim; i++) s += g_cnt[i];
    sh[t] = s;
    __syncthreads();
    #pragma unroll
    for (int off = 1; off < 512; off <<= 1) {
        int v = (t >= off) ? sh[t - off] : 0;
        __syncthreads();
        sh[t] += v;
        __syncthreads();
    }
    int pre = sh[t] - s;                 // exclusive prefix of this chunk
    for (int i = base; i < lim; i++) {
        int c = g_cnt[i];
        g_offs[i] = pre;
        g_cnt[i]  = pre;                 // cursor for placement
        pre += c;
    }
    if (t == 0) g_offs[N] = E;
}

// Counting-sort placement of edges by dst
__global__ void place_k(const int* __restrict__ src,
                        const int* __restrict__ dst,
                        const float* __restrict__ ew, int E) {
    for (int e = blockIdx.x * blockDim.x + threadIdx.x; e < E;
         e += gridDim.x * blockDim.x) {
        int idx = atomicAdd(&g_cnt[dst[e]], 1);
        g_src_s[idx] = src[e];
        g_w_s[idx]   = ew[e];
    }
}

// Segmented gather-reduce: one warp per dst node.
// Stores tf32-ROUNDED bits into g_y (rounding point identical to before).
__global__ void gather_k(const float4* __restrict__ x4,
                         const float* __restrict__ eps, int N) {
    int gt = blockIdx.x * blockDim.x + threadIdx.x;
    int d = gt >> 5;
    if (d >= N) return;
    int lane = gt & 31;

    float s1 = 1.0f + eps[0];
    float4 acc = x4[(long)d * F4 + lane];
    acc.x *= s1; acc.y *= s1; acc.z *= s1; acc.w *= s1;

    int i   = g_offs[d];
    int end = g_offs[d + 1];

    for (; i + 4 <= end; i += 4) {
        int   s0 = g_src_s[i],     s1i = g_src_s[i + 1];
        int   s2 = g_src_s[i + 2], s3  = g_src_s[i + 3];
        float w0 = g_w_s[i],       w1  = g_w_s[i + 1];
        float w2 = g_w_s[i + 2],   w3  = g_w_s[i + 3];
        float4 v0 = x4[(long)s0  * F4 + lane];
        float4 v1 = x4[(long)s1i * F4 + lane];
        float4 v2 = x4[(long)s2  * F4 + lane];
        float4 v3 = x4[(long)s3  * F4 + lane];
        acc.x = fmaf(w0, v0.x, acc.x); acc.y = fmaf(w0, v0.y, acc.y);
        acc.z = fmaf(w0, v0.z, acc.z); acc.w = fmaf(w0, v0.w, acc.w);
        acc.x = fmaf(w1, v1.x, acc.x); acc.y = fmaf(w1, v1.y, acc.y);
        acc.z = fmaf(w1, v1.z, acc.z); acc.w = fmaf(w1, v1.w, acc.w);
        acc.x = fmaf(w2, v2.x, acc.x); acc.y = fmaf(w2, v2.y, acc.y);
        acc.z = fmaf(w2, v2.z, acc.z); acc.w = fmaf(w2, v2.w, acc.w);
        acc.x = fmaf(w3, v3.x, acc.x); acc.y = fmaf(w3, v3.y, acc.y);
        acc.z = fmaf(w3, v3.z, acc.z); acc.w = fmaf(w3, v3.w, acc.w);
    }
    for (; i < end; i++) {
        int   s = g_src_s[i];
        float w = g_w_s[i];
        float4 v = x4[(long)s * F4 + lane];
        acc.x = fmaf(w, v.x, acc.x); acc.y = fmaf(w, v.y, acc.y);
        acc.z = fmaf(w, v.z, acc.z); acc.w = fmaf(w, v.w, acc.w);
    }
    ((float4*)g_y)[(long)d * F4 + lane] = f2tf4(acc);
}

// ---------------------------------------------------------------------------
__device__ __forceinline__ void mma_tf32(float c[4],
                                         unsigned a0, unsigned a1,
                                         unsigned a2, unsigned a3,
                                         unsigned b0, unsigned b1) {
    asm volatile(
        "mma.sync.aligned.m16n8k8.row.col.f32.tf32.tf32.f32 "
        "{%0,%1,%2,%3}, {%4,%5,%6,%7}, {%8,%9}, {%0,%1,%2,%3};"
        : "+f"(c[0]), "+f"(c[1]), "+f"(c[2]), "+f"(c[3])
        : "r"(a0), "r"(a1), "r"(a2), "r"(a3), "r"(b0), "r"(b1));
}

// ---------------------------------------------------------------------------
// Fused tf32 tensor-core MLP — 512 threads, 16 warps.
// Staging is pure float4 copies (W pre-converted, y pre-rounded).
__global__ void __launch_bounds__(512, 2)
gemm_tc(const float* __restrict__ b1, const float* __restrict__ b2,
        float4* __restrict__ out4, int N) {
    extern __shared__ float smem[];
    float* ysm = smem;                    // TROW x PAD
    float* wsm = smem + TROW * PAD;       // F x PAD

    int tid  = threadIdx.x;
    int lane = tid & 31;
    int w    = tid >> 5;                  // 0..15
    int g    = lane >> 2;                 // 0..7
    int tig  = lane & 3;                  // 0..3
    int f0   = (w & 7) * 16;              // feature base
    int nb   = (w >> 3) * 32;             // node base (0 or 32)
    int row0 = blockIdx.x * TROW;

    // ---- Stage W1 and y tile (pure float4 copies) ----
    for (int i = tid; i < F * F4; i += 512) {
        int k = i >> 5, c = i & 31;
        ((float4*)(wsm + k * PAD))[c] = ((const float4*)g_w1t)[i];
    }
    for (int i = tid; i < TROW * F4; i += 512) {
        int r = i >> 5, c = i & 31;
        int gr = row0 + r;
        float4 v = (gr < N) ? ((const float4*)g_y)[(long)gr * F4 + c]
                            : make_float4(0.f, 0.f, 0.f, 0.f);
        ((float4*)(ysm + r * PAD))[c] = v;
    }
    __syncthreads();

    float acc[4][4];
    {
        float bl = b1[f0 + g], bh = b1[f0 + g + 8];
        #pragma unroll
        for (int nt = 0; nt < 4; nt++) {
            acc[nt][0] = bl; acc[nt][1] = bl; acc[nt][2] = bh; acc[nt][3] = bh;
        }
    }
    #pragma unroll
    for (int ks = 0; ks < 16; ks++) {
        int kb = ks * 8;
        unsigned a0 = __float_as_uint(wsm[(kb + tig)     * PAD + f0 + g]);
        unsigned a1 = __float_as_uint(wsm[(kb + tig)     * PAD + f0 + g + 8]);
        unsigned a2 = __float_as_uint(wsm[(kb + tig + 4) * PAD + f0 + g]);
        unsigned a3 = __float_as_uint(wsm[(kb + tig + 4) * PAD + f0 + g + 8]);
        #pragma unroll
        for (int nt = 0; nt < 4; nt++) {
            unsigned b0 = __float_as_uint(ysm[(nb + nt * 8 + g) * PAD + kb + tig]);
            unsigned b1r = __float_as_uint(ysm[(nb + nt * 8 + g) * PAD + kb + tig + 4]);
            mma_tf32(acc[nt], a0, a1, a2, a3, b0, b1r);
        }
    }
    #pragma unroll
    for (int nt = 0; nt < 4; nt++)
        #pragma unroll
        for (int j = 0; j < 4; j++)
            acc[nt][j] = fmaxf(acc[nt][j], 0.0f);

    __syncthreads();   // all reads of ysm/wsm done

    // ---- h1 (tf32, scattered scalar stores) -> ysm; W2 -> wsm ----
    #pragma unroll
    for (int nt = 0; nt < 4; nt++) {
        int r0r = (nb + nt * 8 + 2 * tig) * PAD;
        int r1r = (nb + nt * 8 + 2 * tig + 1) * PAD;
        ysm[r0r + f0 + g]     = __uint_as_float(f2tf(acc[nt][0]));
        ysm[r1r + f0 + g]     = __uint_as_float(f2tf(acc[nt][1]));
        ysm[r0r + f0 + g + 8] = __uint_as_float(f2tf(acc[nt][2]));
        ysm[r1r + f0 + g + 8] = __uint_as_float(f2tf(acc[nt][3]));
    }
    for (int i = tid; i < F * F4; i += 512) {
        int k = i >> 5, c = i & 31;
        ((float4*)(wsm + k * PAD))[c] = ((const float4*)g_w2t)[i];
    }
    __syncthreads();

    {
        float bl = b2[f0 + g], bh = b2[f0 + g + 8];
        #pragma unroll
        for (int nt = 0; nt < 4; nt++) {
            acc[nt][0] = bl; acc[nt][1] = bl; acc[nt][2] = bh; acc[nt][3] = bh;
        }
    }
    #pragma unroll
    for (int ks = 0; ks < 16; ks++) {
        int kb = ks * 8;
        unsigned a0 = __float_as_uint(wsm[(kb + tig)     * PAD + f0 + g]);
        unsigned a1 = __float_as_uint(wsm[(kb + tig)     * PAD + f0 + g + 8]);
        unsigned a2 = __float_as_uint(wsm[(kb + tig + 4) * PAD + f0 + g]);
        unsigned a3 = __float_as_uint(wsm[(kb + tig + 4) * PAD + f0 + g + 8]);
        #pragma unroll
        for (int nt = 0; nt < 4; nt++) {
            unsigned b0 = __float_as_uint(ysm[(nb + nt * 8 + g) * PAD + kb + tig]);
            unsigned b1r = __float_as_uint(ysm[(nb + nt * 8 + g) * PAD + kb + tig + 4]);
            mma_tf32(acc[nt], a0, a1, a2, a3, b0, b1r);
        }
    }
    __syncthreads();   // all reads of ysm done

    // ---- h2 (full fp32) -> ysm[node][feat] for coalesced store ----
    #pragma unroll
    for (int nt = 0; nt < 4; nt++) {
        int r0r = (nb + nt * 8 + 2 * tig) * PAD;
        int r1r = (nb + nt * 8 + 2 * tig + 1) * PAD;
        ysm[r0r + f0 + g]     = acc[nt][0];
        ysm[r1r + f0 + g]     = acc[nt][1];
        ysm[r0r + f0 + g + 8] = acc[nt][2];
        ysm[r1r + f0 + g + 8] = acc[nt][3];
    }
    __syncthreads();

    // ---- Coalesced store + BN column partials (mask phantom rows) ----
    float cs[4] = {0.f, 0.f, 0.f, 0.f};
    float cq[4] = {0.f, 0.f, 0.f, 0.f};
    int c4 = tid & 31;
    int ty = tid >> 5;                    // 0..15
    #pragma unroll
    for (int j = 0; j < 4; j++) {
        int r = ty + j * 16;
        int gr = row0 + r;
        if (gr < N) {
            float4 v = ((const float4*)(ysm + r * PAD))[c4];
            out4[(long)gr * F4 + c4] = v;
            cs[0] += v.x; cs[1] += v.y; cs[2] += v.z; cs[3] += v.w;
            cq[0] += v.x * v.x; cq[1] += v.y * v.y;
            cq[2] += v.z * v.z; cq[3] += v.w * v.w;
        }
    }
    __syncthreads();   // done with ysm/wsm; reuse wsm for reduction
    #pragma unroll
    for (int j = 0; j < 4; j++) {
        wsm[ty * F + c4 * 4 + j]          = cs[j];
        wsm[16 * F + ty * F + c4 * 4 + j] = cq[j];
    }
    __syncthreads();
    if (tid < F) {
        float s = 0.f, q = 0.f;
        #pragma unroll
        for (int t = 0; t < 16; t++) {
            s += wsm[t * F + tid];
            q += wsm[16 * F + t * F + tid];
        }
        atomicAdd(&g_sum[tid], s);
        atomicAdd(&g_sumsq[tid], q);
    }
}

// ---------------------------------------------------------------------------
__global__ void bn_k(float4* __restrict__ out4,
                     const float4* __restrict__ gamma4,
                     const float4* __restrict__ beta4, int N) {
    float invN = 1.0f / (float)N;
    for (int i = blockIdx.x * blockDim.x + threadIdx.x; i < N * F4;
         i += gridDim.x * blockDim.x) {
        int c = i & 31;
        float4 s = ((const float4*)g_sum)[c];
        float4 q = ((const float4*)g_sumsq)[c];
        float4 g = gamma4[c];
        float4 b = beta4[c];
        float4 v = out4[i];

        float m, var, is;
        m = s.x * invN; var = q.x * invN - m * m; is = rsqrtf(var + 1e-5f);
        v.x = (v.x - m) * is * g.x + b.x;
        m = s.y * invN; var = q.y * invN - m * m; is = rsqrtf(var + 1e-5f);
        v.y = (v.y - m) * is * g.y + b.y;
        m = s.z * invN; var = q.z * invN - m * m; is = rsqrtf(var + 1e-5f);
        v.z = (v.z - m) * is * g.z + b.z;
        m = s.w * invN; var = q.w * invN - m * m; is = rsqrtf(var + 1e-5f);
        v.w = (v.w - m) * is * g.w + b.w;

        out4[i] = v;
    }
}

// ---------------------------------------------------------------------------
extern "C" void kernel_launch(void* const* d_in, const int* in_sizes, int n_in,
                              void* d_out, int out_size) {
    const float* x     = (const float*)d_in[0];
    const float* ew    = (const float*)d_in[1];
    const float* W1    = (const float*)d_in[2];
    const float* b1    = (const float*)d_in[3];
    const float* W2    = (const float*)d_in[4];
    const float* b2    = (const float*)d_in[5];
    const float* eps   = (const float*)d_in[6];
    const float* gamma = (const float*)d_in[7];
    const float* beta  = (const float*)d_in[8];
    const int*   src   = (const int*)d_in[9];
    const int*   dst   = (const int*)d_in[10];

    int N = in_sizes[0] / F;
    int E = in_sizes[1];
    float* out = (float*)d_out;

    int smem_bytes = (TROW * PAD + F * PAD) * (int)sizeof(float);
    cudaFuncSetAttribute(gemm_tc, cudaFuncAttributeMaxDynamicSharedMemorySize,
                         smem_bytes);

    setup_k<<<(N + 255) / 256, 256>>>((const float4*)W1, (const float4*)W2, N);
    hist_k<<<1184, 256>>>(dst, E);
    scan_k<<<1, 512>>>(N, E);
    place_k<<<1184, 256>>>(src, dst, ew, E);
    gather_k<<<(N * 32 + 255) / 256, 256>>>((const float4*)x, eps, N);

    int nblk = (N + TROW - 1) / TROW;
    gemm_tc<<<nblk, 512, smem_bytes>>>(b1, b2, (float4*)out, N);

    bn_k<<<1184, 256>>>((float4*)out, (const float4*)gamma,
                        (const float4*)beta, N);
}

// round 8
// speedup vs baseline: 1.4848x; 1.4848x over previous
#include <cuda_runtime.h>

#define F     128
#define F4    32
#define NMAX  50000
#define EMAX  800000
#define TROW  64          // node rows per gemm block
#define PAD   132         // padded row length (floats) -> conflict-free fragments

// Scratch (allocation-free rule: __device__ globals)
__device__ __align__(16) float g_y[NMAX * F];      // tf32-rounded aggregated feats
__device__ __align__(16) float g_w1t[F * F];       // tf32-rounded W1
__device__ __align__(16) float g_w2t[F * F];       // tf32-rounded W2
__device__ __align__(16) float g_sum[F];
__device__ __align__(16) float g_sumsq[F];
__device__ int   g_cnt[NMAX];                      // histogram, then cursor
__device__ int   g_offs[NMAX + 1];                 // segment offsets
__device__ int   g_bsum[64];                       // scan block sums
__device__ int   g_src_s[EMAX];                    // dst-sorted edge sources
__device__ float g_w_s[EMAX];                      // dst-sorted edge weights

// ---------------------------------------------------------------------------
__device__ __forceinline__ unsigned f2tf(float f) {
    unsigned u;
    asm("cvt.rna.tf32.f32 %0, %1;" : "=r"(u) : "f"(f));
    return u;
}
__device__ __forceinline__ float4 f2tf4(float4 v) {
    return make_float4(__uint_as_float(f2tf(v.x)), __uint_as_float(f2tf(v.y)),
                       __uint_as_float(f2tf(v.z)), __uint_as_float(f2tf(v.w)));
}

// Setup: zero counters/stats + one-time tf32 conversion of W1, W2
__global__ void setup_k(const float4* __restrict__ W1,
                        const float4* __restrict__ W2, int N) {
    int i = blockIdx.x * blockDim.x + threadIdx.x;
    if (i < N) g_cnt[i] = 0;
    if (i < F) { g_sum[i] = 0.0f; g_sumsq[i] = 0.0f; }
    if (i < F * F4) {
        ((float4*)g_w1t)[i] = f2tf4(W1[i]);
        ((float4*)g_w2t)[i] = f2tf4(W2[i]);
    }
}

__global__ void hist_k(const int* __restrict__ dst, int E) {
    for (int e = blockIdx.x * blockDim.x + threadIdx.x; e < E;
         e += gridDim.x * blockDim.x)
        atomicAdd(&g_cnt[dst[e]], 1);
}

// Coalesced block-local exclusive scan (1024/block), per R4 (proven fast)
__global__ void scan1_k(int N) {
    __shared__ int sh[1024];
    int t = threadIdx.x;
    int i = blockIdx.x * 1024 + t;
    int c = (i < N) ? g_cnt[i] : 0;
    sh[t] = c;
    __syncthreads();
    #pragma unroll
    for (int off = 1; off < 1024; off <<= 1) {
        int v = (t >= off) ? sh[t - off] : 0;
        __syncthreads();
        sh[t] += v;
        __syncthreads();
    }
    if (i < N) g_offs[i] = sh[t] - c;     // exclusive, block-local
    if (t == 1023) g_bsum[blockIdx.x] = sh[1023];
}

// Single block: prefix the <=64 block sums, then COALESCED fixup over N
__global__ void scan2b_k(int N, int E, int B1) {
    __shared__ int bs[64];
    int t = threadIdx.x;
    if (t < 64) bs[t] = (t < B1) ? g_bsum[t] : 0;
    __syncthreads();
    if (t == 0) {
        int run = 0;
        for (int j = 0; j < B1; j++) { int c = bs[j]; bs[j] = run; run += c; }
    }
    __syncthreads();
    for (int i = t; i < N; i += blockDim.x) {   // coalesced: stride = blockDim
        int o = g_offs[i] + bs[i >> 10];
        g_offs[i] = o;
        g_cnt[i]  = o;                          // cursor for placement
    }
    if (t == 0) g_offs[N] = E;
}

// Counting-sort placement of edges by dst
__global__ void place_k(const int* __restrict__ src,
                        const int* __restrict__ dst,
                        const float* __restrict__ ew, int E) {
    for (int e = blockIdx.x * blockDim.x + threadIdx.x; e < E;
         e += gridDim.x * blockDim.x) {
        int idx = atomicAdd(&g_cnt[dst[e]], 1);
        g_src_s[idx] = src[e];
        g_w_s[idx]   = ew[e];
    }
}

// Segmented gather-reduce: one warp per dst node.
// Stores tf32-ROUNDED bits into g_y.
__global__ void gather_k(const float4* __restrict__ x4,
                         const float* __restrict__ eps, int N) {
    int gt = blockIdx.x * blockDim.x + threadIdx.x;
    int d = gt >> 5;
    if (d >= N) return;
    int lane = gt & 31;

    float s1 = 1.0f + eps[0];
    float4 acc = x4[(long)d * F4 + lane];
    acc.x *= s1; acc.y *= s1; acc.z *= s1; acc.w *= s1;

    int i   = g_offs[d];
    int end = g_offs[d + 1];

    for (; i + 4 <= end; i += 4) {
        int   s0 = g_src_s[i],     s1i = g_src_s[i + 1];
        int   s2 = g_src_s[i + 2], s3  = g_src_s[i + 3];
        float w0 = g_w_s[i],       w1  = g_w_s[i + 1];
        float w2 = g_w_s[i + 2],   w3  = g_w_s[i + 3];
        float4 v0 = x4[(long)s0  * F4 + lane];
        float4 v1 = x4[(long)s1i * F4 + lane];
        float4 v2 = x4[(long)s2  * F4 + lane];
        float4 v3 = x4[(long)s3  * F4 + lane];
        acc.x = fmaf(w0, v0.x, acc.x); acc.y = fmaf(w0, v0.y, acc.y);
        acc.z = fmaf(w0, v0.z, acc.z); acc.w = fmaf(w0, v0.w, acc.w);
        acc.x = fmaf(w1, v1.x, acc.x); acc.y = fmaf(w1, v1.y, acc.y);
        acc.z = fmaf(w1, v1.z, acc.z); acc.w = fmaf(w1, v1.w, acc.w);
        acc.x = fmaf(w2, v2.x, acc.x); acc.y = fmaf(w2, v2.y, acc.y);
        acc.z = fmaf(w2, v2.z, acc.z); acc.w = fmaf(w2, v2.w, acc.w);
        acc.x = fmaf(w3, v3.x, acc.x); acc.y = fmaf(w3, v3.y, acc.y);
        acc.z = fmaf(w3, v3.z, acc.z); acc.w = fmaf(w3, v3.w, acc.w);
    }
    for (; i < end; i++) {
        int   s = g_src_s[i];
        float w = g_w_s[i];
        float4 v = x4[(long)s * F4 + lane];
        acc.x = fmaf(w, v.x, acc.x); acc.y = fmaf(w, v.y, acc.y);
        acc.z = fmaf(w, v.z, acc.z); acc.w = fmaf(w, v.w, acc.w);
    }
    ((float4*)g_y)[(long)d * F4 + lane] = f2tf4(acc);
}

// ---------------------------------------------------------------------------
__device__ __forceinline__ void mma_tf32(float c[4],
                                         unsigned a0, unsigned a1,
                                         unsigned a2, unsigned a3,
                                         unsigned b0, unsigned b1) {
    asm volatile(
        "mma.sync.aligned.m16n8k8.row.col.f32.tf32.tf32.f32 "
        "{%0,%1,%2,%3}, {%4,%5,%6,%7}, {%8,%9}, {%0,%1,%2,%3};"
        : "+f"(c[0]), "+f"(c[1]), "+f"(c[2]), "+f"(c[3])
        : "r"(a0), "r"(a1), "r"(a2), "r"(a3), "r"(b0), "r"(b1));
}

// ---------------------------------------------------------------------------
// Fused tf32 tensor-core MLP — 512 threads, 16 warps.
// Staging is pure float4 copies (W pre-converted, y pre-rounded).
__global__ void __launch_bounds__(512, 2)
gemm_tc(const float* __restrict__ b1, const float* __restrict__ b2,
        float4* __restrict__ out4, int N) {
    extern __shared__ float smem[];
    float* ysm = smem;                    // TROW x PAD
    float* wsm = smem + TROW * PAD;       // F x PAD

    int tid  = threadIdx.x;
    int lane = tid & 31;
    int w    = tid >> 5;                  // 0..15
    int g    = lane >> 2;                 // 0..7
    int tig  = lane & 3;                  // 0..3
    int f0   = (w & 7) * 16;              // feature base
    int nb   = (w >> 3) * 32;             // node base (0 or 32)
    int row0 = blockIdx.x * TROW;

    // ---- Stage W1 and y tile (pure float4 copies) ----
    for (int i = tid; i < F * F4; i += 512) {
        int k = i >> 5, c = i & 31;
        ((float4*)(wsm + k * PAD))[c] = ((const float4*)g_w1t)[i];
    }
    for (int i = tid; i < TROW * F4; i += 512) {
        int r = i >> 5, c = i & 31;
        int gr = row0 + r;
        float4 v = (gr < N) ? ((const float4*)g_y)[(long)gr * F4 + c]
                            : make_float4(0.f, 0.f, 0.f, 0.f);
        ((float4*)(ysm + r * PAD))[c] = v;
    }
    __syncthreads();

    float acc[4][4];
    {
        float bl = b1[f0 + g], bh = b1[f0 + g + 8];
        #pragma unroll
        for (int nt = 0; nt < 4; nt++) {
            acc[nt][0] = bl; acc[nt][1] = bl; acc[nt][2] = bh; acc[nt][3] = bh;
        }
    }
    #pragma unroll
    for (int ks = 0; ks < 16; ks++) {
        int kb = ks * 8;
        unsigned a0 = __float_as_uint(wsm[(kb + tig)     * PAD + f0 + g]);
        unsigned a1 = __float_as_uint(wsm[(kb + tig)     * PAD + f0 + g + 8]);
        unsigned a2 = __float_as_uint(wsm[(kb + tig + 4) * PAD + f0 + g]);
        unsigned a3 = __float_as_uint(wsm[(kb + tig + 4) * PAD + f0 + g + 8]);
        #pragma unroll
        for (int nt = 0; nt < 4; nt++) {
            unsigned b0 = __float_as_uint(ysm[(nb + nt * 8 + g) * PAD + kb + tig]);
            unsigned b1r = __float_as_uint(ysm[(nb + nt * 8 + g) * PAD + kb + tig + 4]);
            mma_tf32(acc[nt], a0, a1, a2, a3, b0, b1r);
        }
    }
    #pragma unroll
    for (int nt = 0; nt < 4; nt++)
        #pragma unroll
        for (int j = 0; j < 4; j++)
            acc[nt][j] = fmaxf(acc[nt][j], 0.0f);

    __syncthreads();   // all reads of ysm/wsm done

    // ---- h1 (tf32) -> ysm; W2 -> wsm ----
    #pragma unroll
    for (int nt = 0; nt < 4; nt++) {
        int r0r = (nb + nt * 8 + 2 * tig) * PAD;
        int r1r = (nb + nt * 8 + 2 * tig + 1) * PAD;
        ysm[r0r + f0 + g]     = __uint_as_float(f2tf(acc[nt][0]));
        ysm[r1r + f0 + g]     = __uint_as_float(f2tf(acc[nt][1]));
        ysm[r0r + f0 + g + 8] = __uint_as_float(f2tf(acc[nt][2]));
        ysm[r1r + f0 + g + 8] = __uint_as_float(f2tf(acc[nt][3]));
    }
    for (int i = tid; i < F * F4; i += 512) {
        int k = i >> 5, c = i & 31;
        ((float4*)(wsm + k * PAD))[c] = ((const float4*)g_w2t)[i];
    }
    __syncthreads();

    {
        float bl = b2[f0 + g], bh = b2[f0 + g + 8];
        #pragma unroll
        for (int nt = 0; nt < 4; nt++) {
            acc[nt][0] = bl; acc[nt][1] = bl; acc[nt][2] = bh; acc[nt][3] = bh;
        }
    }
    #pragma unroll
    for (int ks = 0; ks < 16; ks++) {
        int kb = ks * 8;
        unsigned a0 = __float_as_uint(wsm[(kb + tig)     * PAD + f0 + g]);
        unsigned a1 = __float_as_uint(wsm[(kb + tig)     * PAD + f0 + g + 8]);
        unsigned a2 = __float_as_uint(wsm[(kb + tig + 4) * PAD + f0 + g]);
        unsigned a3 = __float_as_uint(wsm[(kb + tig + 4) * PAD + f0 + g + 8]);
        #pragma unroll
        for (int nt = 0; nt < 4; nt++) {
            unsigned b0 = __float_as_uint(ysm[(nb + nt * 8 + g) * PAD + kb + tig]);
            unsigned b1r = __float_as_uint(ysm[(nb + nt * 8 + g) * PAD + kb + tig + 4]);
            mma_tf32(acc[nt], a0, a1, a2, a3, b0, b1r);
        }
    }
    __syncthreads();   // all reads of ysm done

    // ---- h2 (full fp32) -> ysm[node][feat] for coalesced store ----
    #pragma unroll
    for (int nt = 0; nt < 4; nt++) {
        int r0r = (nb + nt * 8 + 2 * tig) * PAD;
        int r1r = (nb + nt * 8 + 2 * tig + 1) * PAD;
        ysm[r0r + f0 + g]     = acc[nt][0];
        ysm[r1r + f0 + g]     = acc[nt][1];
        ysm[r0r + f0 + g + 8] = acc[nt][2];
        ysm[r1r + f0 + g + 8] = acc[nt][3];
    }
    __syncthreads();

    // ---- Coalesced store + BN column partials (mask phantom rows) ----
    float cs[4] = {0.f, 0.f, 0.f, 0.f};
    float cq[4] = {0.f, 0.f, 0.f, 0.f};
    int c4 = tid & 31;
    int ty = tid >> 5;                    // 0..15
    #pragma unroll
    for (int j = 0; j < 4; j++) {
        int r = ty + j * 16;
        int gr = row0 + r;
        if (gr < N) {
            float4 v = ((const float4*)(ysm + r * PAD))[c4];
            out4[(long)gr * F4 + c4] = v;
            cs[0] += v.x; cs[1] += v.y; cs[2] += v.z; cs[3] += v.w;
            cq[0] += v.x * v.x; cq[1] += v.y * v.y;
            cq[2] += v.z * v.z; cq[3] += v.w * v.w;
        }
    }
    __syncthreads();   // done with ysm/wsm; reuse wsm for reduction
    #pragma unroll
    for (int j = 0; j < 4; j++) {
        wsm[ty * F + c4 * 4 + j]          = cs[j];
        wsm[16 * F + ty * F + c4 * 4 + j] = cq[j];
    }
    __syncthreads();
    if (tid < F) {
        float s = 0.f, q = 0.f;
        #pragma unroll
        for (int t = 0; t < 16; t++) {
            s += wsm[t * F + tid];
            q += wsm[16 * F + t * F + tid];
        }
        atomicAdd(&g_sum[tid], s);
        atomicAdd(&g_sumsq[tid], q);
    }
}

// ---------------------------------------------------------------------------
__global__ void bn_k(float4* __restrict__ out4,
                     const float4* __restrict__ gamma4,
                     const float4* __restrict__ beta4, int N) {
    float invN = 1.0f / (float)N;
    for (int i = blockIdx.x * blockDim.x + threadIdx.x; i < N * F4;
         i += gridDim.x * blockDim.x) {
        int c = i & 31;
        float4 s = ((const float4*)g_sum)[c];
        float4 q = ((const float4*)g_sumsq)[c];
        float4 g = gamma4[c];
        float4 b = beta4[c];
        float4 v = out4[i];

        float m, var, is;
        m = s.x * invN; var = q.x * invN - m * m; is = rsqrtf(var + 1e-5f);
        v.x = (v.x - m) * is * g.x + b.x;
        m = s.y * invN; var = q.y * invN - m * m; is = rsqrtf(var + 1e-5f);
        v.y = (v.y - m) * is * g.y + b.y;
        m = s.z * invN; var = q.z * invN - m * m; is = rsqrtf(var + 1e-5f);
        v.z = (v.z - m) * is * g.z + b.z;
        m = s.w * invN; var = q.w * invN - m * m; is = rsqrtf(var + 1e-5f);
        v.w = (v.w - m) * is * g.w + b.w;

        out4[i] = v;
    }
}

// ---------------------------------------------------------------------------
extern "C" void kernel_launch(void* const* d_in, const int* in_sizes, int n_in,
                              void* d_out, int out_size) {
    const float* x     = (const float*)d_in[0];
    const float* ew    = (const float*)d_in[1];
    const float* W1    = (const float*)d_in[2];
    const float* b1    = (const float*)d_in[3];
    const float* W2    = (const float*)d_in[4];
    const float* b2    = (const float*)d_in[5];
    const float* eps   = (const float*)d_in[6];
    const float* gamma = (const float*)d_in[7];
    const float* beta  = (const float*)d_in[8];
    const int*   src   = (const int*)d_in[9];
    const int*   dst   = (const int*)d_in[10];

    int N = in_sizes[0] / F;
    int E = in_sizes[1];
    float* out = (float*)d_out;

    int smem_bytes = (TROW * PAD + F * PAD) * (int)sizeof(float);
    cudaFuncSetAttribute(gemm_tc, cudaFuncAttributeMaxDynamicSharedMemorySize,
                         smem_bytes);

    int B1 = (N + 1023) / 1024;

    setup_k<<<(N + 255) / 256, 256>>>((const float4*)W1, (const float4*)W2, N);
    hist_k<<<1184, 256>>>(dst, E);
    scan1_k<<<B1, 1024>>>(N);
    scan2b_k<<<1, 1024>>>(N, E, B1);
    place_k<<<1184, 256>>>(src, dst, ew, E);
    gather_k<<<(N * 32 + 255) / 256, 256>>>((const float4*)x, eps, N);

    int nblk = (N + TROW - 1) / TROW;
    gemm_tc<<<nblk, 512, smem_bytes>>>(b1, b2, (float4*)out, N);

    bn_k<<<1184, 256>>>((float4*)out, (const float4*)gamma,
                        (const float4*)beta, N);
}

// round 9
// speedup vs baseline: 1.6190x; 1.0903x over previous
#include <cuda_runtime.h>

#define F     128
#define F4    32
#define NMAX  50000
#define EMAX  800000
#define TROW  64          // node rows per gemm block
#define PAD   132         // padded row length (floats) -> conflict-free fragments

// Scratch (allocation-free rule: __device__ globals)
__device__ __align__(16) float g_y[NMAX * F];      // tf32-rounded aggregated feats
__device__ __align__(16) float g_w1t[F * F];       // tf32-rounded W1
__device__ __align__(16) float g_w2t[F * F];       // tf32-rounded W2
__device__ __align__(16) float g_sum[F];
__device__ __align__(16) float g_sumsq[F];
__device__ int   g_cnt[NMAX];                      // histogram, then cursor
__device__ int   g_offs[NMAX + 1];                 // segment offsets
__device__ int   g_bsum[64];                       // scan block sums
__device__ int   g_src_s[EMAX];                    // dst-sorted edge sources
__device__ float g_w_s[EMAX];                      // dst-sorted edge weights

// ---------------------------------------------------------------------------
__device__ __forceinline__ unsigned f2tf(float f) {
    unsigned u;
    asm("cvt.rna.tf32.f32 %0, %1;" : "=r"(u) : "f"(f));
    return u;
}
__device__ __forceinline__ float4 f2tf4(float4 v) {
    return make_float4(__uint_as_float(f2tf(v.x)), __uint_as_float(f2tf(v.y)),
                       __uint_as_float(f2tf(v.z)), __uint_as_float(f2tf(v.w)));
}

// Setup: zero counters/stats + one-time tf32 conversion of W1, W2
__global__ void setup_k(const float4* __restrict__ W1,
                        const float4* __restrict__ W2, int N) {
    int i = blockIdx.x * blockDim.x + threadIdx.x;
    if (i < N) g_cnt[i] = 0;
    if (i < F) { g_sum[i] = 0.0f; g_sumsq[i] = 0.0f; }
    if (i < F * F4) {
        ((float4*)g_w1t)[i] = f2tf4(W1[i]);
        ((float4*)g_w2t)[i] = f2tf4(W2[i]);
    }
}

__global__ void hist_k(const int* __restrict__ dst, int E) {
    for (int e = blockIdx.x * blockDim.x + threadIdx.x; e < E;
         e += gridDim.x * blockDim.x)
        atomicAdd(&g_cnt[dst[e]], 1);
}

// Coalesced block-local exclusive scan (1024/block) — R4-proven
__global__ void scan1_k(int N) {
    __shared__ int sh[1024];
    int t = threadIdx.x;
    int i = blockIdx.x * 1024 + t;
    int c = (i < N) ? g_cnt[i] : 0;
    sh[t] = c;
    __syncthreads();
    #pragma unroll
    for (int off = 1; off < 1024; off <<= 1) {
        int v = (t >= off) ? sh[t - off] : 0;
        __syncthreads();
        sh[t] += v;
        __syncthreads();
    }
    if (i < N) g_offs[i] = sh[t] - c;     // exclusive, block-local
    if (t == 1023) g_bsum[blockIdx.x] = sh[1023];
}

// 64-thread prefix over the block sums — R4-proven
__global__ void scan2_k(int B1) {
    __shared__ int sh[64];
    int t = threadIdx.x;
    int v = (t < B1) ? g_bsum[t] : 0;
    sh[t] = v;
    __syncthreads();
    #pragma unroll
    for (int off = 1; off < 64; off <<= 1) {
        int u = (t >= off) ? sh[t - off] : 0;
        __syncthreads();
        sh[t] += u;
        __syncthreads();
    }
    if (t < B1) g_bsum[t] = sh[t] - v;    // exclusive over block totals
}

// Multi-block coalesced fixup — R4-proven
__global__ void scan3_k(int N, int E) {
    int i = blockIdx.x * blockDim.x + threadIdx.x;
    if (i < N) {
        int o = g_offs[i] + g_bsum[i >> 10];
        g_offs[i] = o;
        g_cnt[i]  = o;                    // cursor for placement
    }
    if (i == 0) g_offs[N] = E;
}

// Counting-sort placement of edges by dst
__global__ void place_k(const int* __restrict__ src,
                        const int* __restrict__ dst,
                        const float* __restrict__ ew, int E) {
    for (int e = blockIdx.x * blockDim.x + threadIdx.x; e < E;
         e += gridDim.x * blockDim.x) {
        int idx = atomicAdd(&g_cnt[dst[e]], 1);
        g_src_s[idx] = src[e];
        g_w_s[idx]   = ew[e];
    }
}

// Segmented gather-reduce: one warp per dst node.
// Stores tf32-ROUNDED bits into g_y.
__global__ void gather_k(const float4* __restrict__ x4,
                         const float* __restrict__ eps, int N) {
    int gt = blockIdx.x * blockDim.x + threadIdx.x;
    int d = gt >> 5;
    if (d >= N) return;
    int lane = gt & 31;

    float s1 = 1.0f + eps[0];
    float4 acc = x4[(long)d * F4 + lane];
    acc.x *= s1; acc.y *= s1; acc.z *= s1; acc.w *= s1;

    int i   = g_offs[d];
    int end = g_offs[d + 1];

    for (; i + 4 <= end; i += 4) {
        int   s0 = g_src_s[i],     s1i = g_src_s[i + 1];
        int   s2 = g_src_s[i + 2], s3  = g_src_s[i + 3];
        float w0 = g_w_s[i],       w1  = g_w_s[i + 1];
        float w2 = g_w_s[i + 2],   w3  = g_w_s[i + 3];
        float4 v0 = x4[(long)s0  * F4 + lane];
        float4 v1 = x4[(long)s1i * F4 + lane];
        float4 v2 = x4[(long)s2  * F4 + lane];
        float4 v3 = x4[(long)s3  * F4 + lane];
        acc.x = fmaf(w0, v0.x, acc.x); acc.y = fmaf(w0, v0.y, acc.y);
        acc.z = fmaf(w0, v0.z, acc.z); acc.w = fmaf(w0, v0.w, acc.w);
        acc.x = fmaf(w1, v1.x, acc.x); acc.y = fmaf(w1, v1.y, acc.y);
        acc.z = fmaf(w1, v1.z, acc.z); acc.w = fmaf(w1, v1.w, acc.w);
        acc.x = fmaf(w2, v2.x, acc.x); acc.y = fmaf(w2, v2.y, acc.y);
        acc.z = fmaf(w2, v2.z, acc.z); acc.w = fmaf(w2, v2.w, acc.w);
        acc.x = fmaf(w3, v3.x, acc.x); acc.y = fmaf(w3, v3.y, acc.y);
        acc.z = fmaf(w3, v3.z, acc.z); acc.w = fmaf(w3, v3.w, acc.w);
    }
    for (; i < end; i++) {
        int   s = g_src_s[i];
        float w = g_w_s[i];
        float4 v = x4[(long)s * F4 + lane];
        acc.x = fmaf(w, v.x, acc.x); acc.y = fmaf(w, v.y, acc.y);
        acc.z = fmaf(w, v.z, acc.z); acc.w = fmaf(w, v.w, acc.w);
    }
    ((float4*)g_y)[(long)d * F4 + lane] = f2tf4(acc);
}

// ---------------------------------------------------------------------------
__device__ __forceinline__ void mma_tf32(float c[4],
                                         unsigned a0, unsigned a1,
                                         unsigned a2, unsigned a3,
                                         unsigned b0, unsigned b1) {
    asm volatile(
        "mma.sync.aligned.m16n8k8.row.col.f32.tf32.tf32.f32 "
        "{%0,%1,%2,%3}, {%4,%5,%6,%7}, {%8,%9}, {%0,%1,%2,%3};"
        : "+f"(c[0]), "+f"(c[1]), "+f"(c[2]), "+f"(c[3])
        : "r"(a0), "r"(a1), "r"(a2), "r"(a3), "r"(b0), "r"(b1));
}

// ---------------------------------------------------------------------------
// Fused tf32 tensor-core MLP — 512 threads, 16 warps.
// Staging is pure float4 copies (W pre-converted, y pre-rounded).
__global__ void __launch_bounds__(512, 2)
gemm_tc(const float* __restrict__ b1, const float* __restrict__ b2,
        float4* __restrict__ out4, int N) {
    extern __shared__ float smem[];
    float* ysm = smem;                    // TROW x PAD
    float* wsm = smem + TROW * PAD;       // F x PAD

    int tid  = threadIdx.x;
    int lane = tid & 31;
    int w    = tid >> 5;                  // 0..15
    int g    = lane >> 2;                 // 0..7
    int tig  = lane & 3;                  // 0..3
    int f0   = (w & 7) * 16;              // feature base
    int nb   = (w >> 3) * 32;             // node base (0 or 32)
    int row0 = blockIdx.x * TROW;

    // ---- Stage W1 and y tile (pure float4 copies) ----
    for (int i = tid; i < F * F4; i += 512) {
        int k = i >> 5, c = i & 31;
        ((float4*)(wsm + k * PAD))[c] = ((const float4*)g_w1t)[i];
    }
    for (int i = tid; i < TROW * F4; i += 512) {
        int r = i >> 5, c = i & 31;
        int gr = row0 + r;
        float4 v = (gr < N) ? ((const float4*)g_y)[(long)gr * F4 + c]
                            : make_float4(0.f, 0.f, 0.f, 0.f);
        ((float4*)(ysm + r * PAD))[c] = v;
    }
    __syncthreads();

    float acc[4][4];
    {
        float bl = b1[f0 + g], bh = b1[f0 + g + 8];
        #pragma unroll
        for (int nt = 0; nt < 4; nt++) {
            acc[nt][0] = bl; acc[nt][1] = bl; acc[nt][2] = bh; acc[nt][3] = bh;
        }
    }
    #pragma unroll
    for (int ks = 0; ks < 16; ks++) {
        int kb = ks * 8;
        unsigned a0 = __float_as_uint(wsm[(kb + tig)     * PAD + f0 + g]);
        unsigned a1 = __float_as_uint(wsm[(kb + tig)     * PAD + f0 + g + 8]);
        unsigned a2 = __float_as_uint(wsm[(kb + tig + 4) * PAD + f0 + g]);
        unsigned a3 = __float_as_uint(wsm[(kb + tig + 4) * PAD + f0 + g + 8]);
        #pragma unroll
        for (int nt = 0; nt < 4; nt++) {
            unsigned b0 = __float_as_uint(ysm[(nb + nt * 8 + g) * PAD + kb + tig]);
            unsigned b1r = __float_as_uint(ysm[(nb + nt * 8 + g) * PAD + kb + tig + 4]);
            mma_tf32(acc[nt], a0, a1, a2, a3, b0, b1r);
        }
    }
    #pragma unroll
    for (int nt = 0; nt < 4; nt++)
        #pragma unroll
        for (int j = 0; j < 4; j++)
            acc[nt][j] = fmaxf(acc[nt][j], 0.0f);

    __syncthreads();   // all reads of ysm/wsm done

    // ---- h1 (tf32) -> ysm; W2 -> wsm ----
    #pragma unroll
    for (int nt = 0; nt < 4; nt++) {
        int r0r = (nb + nt * 8 + 2 * tig) * PAD;
        int r1r = (nb + nt * 8 + 2 * tig + 1) * PAD;
        ysm[r0r + f0 + g]     = __uint_as_float(f2tf(acc[nt][0]));
        ysm[r1r + f0 + g]     = __uint_as_float(f2tf(acc[nt][1]));
        ysm[r0r + f0 + g + 8] = __uint_as_float(f2tf(acc[nt][2]));
        ysm[r1r + f0 + g + 8] = __uint_as_float(f2tf(acc[nt][3]));
    }
    for (int i = tid; i < F * F4; i += 512) {
        int k = i >> 5, c = i & 31;
        ((float4*)(wsm + k * PAD))[c] = ((const float4*)g_w2t)[i];
    }
    __syncthreads();

    {
        float bl = b2[f0 + g], bh = b2[f0 + g + 8];
        #pragma unroll
        for (int nt = 0; nt < 4; nt++) {
            acc[nt][0] = bl; acc[nt][1] = bl; acc[nt][2] = bh; acc[nt][3] = bh;
        }
    }
    #pragma unroll
    for (int ks = 0; ks < 16; ks++) {
        int kb = ks * 8;
        unsigned a0 = __float_as_uint(wsm[(kb + tig)     * PAD + f0 + g]);
        unsigned a1 = __float_as_uint(wsm[(kb + tig)     * PAD + f0 + g + 8]);
        unsigned a2 = __float_as_uint(wsm[(kb + tig + 4) * PAD + f0 + g]);
        unsigned a3 = __float_as_uint(wsm[(kb + tig + 4) * PAD + f0 + g + 8]);
        #pragma unroll
        for (int nt = 0; nt < 4; nt++) {
            unsigned b0 = __float_as_uint(ysm[(nb + nt * 8 + g) * PAD + kb + tig]);
            unsigned b1r = __float_as_uint(ysm[(nb + nt * 8 + g) * PAD + kb + tig + 4]);
            mma_tf32(acc[nt], a0, a1, a2, a3, b0, b1r);
        }
    }
    __syncthreads();   // all reads of ysm done

    // ---- h2 (full fp32) -> ysm[node][feat] for coalesced store ----
    #pragma unroll
    for (int nt = 0; nt < 4; nt++) {
        int r0r = (nb + nt * 8 + 2 * tig) * PAD;
        int r1r = (nb + nt * 8 + 2 * tig + 1) * PAD;
        ysm[r0r + f0 + g]     = acc[nt][0];
        ysm[r1r + f0 + g]     = acc[nt][1];
        ysm[r0r + f0 + g + 8] = acc[nt][2];
        ysm[r1r + f0 + g + 8] = acc[nt][3];
    }
    __syncthreads();

    // ---- Coalesced store + BN column partials (mask phantom rows) ----
    float cs[4] = {0.f, 0.f, 0.f, 0.f};
    float cq[4] = {0.f, 0.f, 0.f, 0.f};
    int c4 = tid & 31;
    int ty = tid >> 5;                    // 0..15
    #pragma unroll
    for (int j = 0; j < 4; j++) {
        int r = ty + j * 16;
        int gr = row0 + r;
        if (gr < N) {
            float4 v = ((const float4*)(ysm + r * PAD))[c4];
            out4[(long)gr * F4 + c4] = v;
            cs[0] += v.x; cs[1] += v.y; cs[2] += v.z; cs[3] += v.w;
            cq[0] += v.x * v.x; cq[1] += v.y * v.y;
            cq[2] += v.z * v.z; cq[3] += v.w * v.w;
        }
    }
    __syncthreads();   // done with ysm/wsm; reuse wsm for reduction
    #pragma unroll
    for (int j = 0; j < 4; j++) {
        wsm[ty * F + c4 * 4 + j]          = cs[j];
        wsm[16 * F + ty * F + c4 * 4 + j] = cq[j];
    }
    __syncthreads();
    if (tid < F) {
        float s = 0.f, q = 0.f;
        #pragma unroll
        for (int t = 0; t < 16; t++) {
            s += wsm[t * F + tid];
            q += wsm[16 * F + t * F + tid];
        }
        atomicAdd(&g_sum[tid], s);
        atomicAdd(&g_sumsq[tid], q);
    }
}

// ---------------------------------------------------------------------------
__global__ void bn_k(float4* __restrict__ out4,
                     const float4* __restrict__ gamma4,
                     const float4* __restrict__ beta4, int N) {
    float invN = 1.0f / (float)N;
    for (int i = blockIdx.x * blockDim.x + threadIdx.x; i < N * F4;
         i += gridDim.x * blockDim.x) {
        int c = i & 31;
        float4 s = ((const float4*)g_sum)[c];
        float4 q = ((const float4*)g_sumsq)[c];
        float4 g = gamma4[c];
        float4 b = beta4[c];
        float4 v = out4[i];

        float m, var, is;
        m = s.x * invN; var = q.x * invN - m * m; is = rsqrtf(var + 1e-5f);
        v.x = (v.x - m) * is * g.x + b.x;
        m = s.y * invN; var = q.y * invN - m * m; is = rsqrtf(var + 1e-5f);
        v.y = (v.y - m) * is * g.y + b.y;
        m = s.z * invN; var = q.z * invN - m * m; is = rsqrtf(var + 1e-5f);
        v.z = (v.z - m) * is * g.z + b.z;
        m = s.w * invN; var = q.w * invN - m * m; is = rsqrtf(var + 1e-5f);
        v.w = (v.w - m) * is * g.w + b.w;

        out4[i] = v;
    }
}

// ---------------------------------------------------------------------------
extern "C" void kernel_launch(void* const* d_in, const int* in_sizes, int n_in,
                              void* d_out, int out_size) {
    const float* x     = (const float*)d_in[0];
    const float* ew    = (const float*)d_in[1];
    const float* W1    = (const float*)d_in[2];
    const float* b1    = (const float*)d_in[3];
    const float* W2    = (const float*)d_in[4];
    const float* b2    = (const float*)d_in[5];
    const float* eps   = (const float*)d_in[6];
    const float* gamma = (const float*)d_in[7];
    const float* beta  = (const float*)d_in[8];
    const int*   src   = (const int*)d_in[9];
    const int*   dst   = (const int*)d_in[10];

    int N = in_sizes[0] / F;
    int E = in_sizes[1];
    float* out = (float*)d_out;

    int smem_bytes = (TROW * PAD + F * PAD) * (int)sizeof(float);
    cudaFuncSetAttribute(gemm_tc, cudaFuncAttributeMaxDynamicSharedMemorySize,
                         smem_bytes);

    int B1 = (N + 1023) / 1024;

    setup_k<<<(N + 255) / 256, 256>>>((const float4*)W1, (const float4*)W2, N);
    hist_k<<<1184, 256>>>(dst, E);
    scan1_k<<<B1, 1024>>>(N);
    scan2_k<<<1, 64>>>(B1);
    scan3_k<<<(N + 255) / 256, 256>>>(N, E);
    place_k<<<1184, 256>>>(src, dst, ew, E);
    gather_k<<<(N * 32 + 255) / 256, 256>>>((const float4*)x, eps, N);

    int nblk = (N + TROW - 1) / TROW;
    gemm_tc<<<nblk, 512, smem_bytes>>>(b1, b2, (float4*)out, N);

    bn_k<<<1184, 256>>>((float4*)out, (const float4*)gamma,
                        (const float4*)beta, N);
}

// round 10
// speedup vs baseline: 1.6610x; 1.0260x over previous
#include <cuda_runtime.h>

#define F     128
#define F4    32
#define NMAX  50000
#define EMAX  800000
#define TROW  64          // node rows per gemm block
#define PAD   132         // padded row length (floats) -> conflict-free fragments

// Scratch (allocation-free rule: __device__ globals)
__device__ __align__(16) float g_y[NMAX * F];      // tf32-rounded aggregated feats
__device__ __align__(16) float g_w1t[F * F];       // tf32-rounded W1
__device__ __align__(16) float g_w2t[F * F];       // tf32-rounded W2
__device__ __align__(16) float g_sum[F];
__device__ __align__(16) float g_sumsq[F];
__device__ int   g_cnt[NMAX];                      // histogram, then cursor
__device__ int   g_offs[NMAX + 1];                 // segment offsets
__device__ int   g_bsum[64];                       // scan block sums
__device__ __align__(16) int2 g_es[EMAX];          // dst-sorted (src, w) pairs

// ---------------------------------------------------------------------------
__device__ __forceinline__ unsigned f2tf(float f) {
    unsigned u;
    asm("cvt.rna.tf32.f32 %0, %1;" : "=r"(u) : "f"(f));
    return u;
}
__device__ __forceinline__ float4 f2tf4(float4 v) {
    return make_float4(__uint_as_float(f2tf(v.x)), __uint_as_float(f2tf(v.y)),
                       __uint_as_float(f2tf(v.z)), __uint_as_float(f2tf(v.w)));
}

// Setup: zero counters/stats + one-time tf32 conversion of W1, W2
__global__ void setup_k(const float4* __restrict__ W1,
                        const float4* __restrict__ W2, int N) {
    int i = blockIdx.x * blockDim.x + threadIdx.x;
    if (i < N) g_cnt[i] = 0;
    if (i < F) { g_sum[i] = 0.0f; g_sumsq[i] = 0.0f; }
    if (i < F * F4) {
        ((float4*)g_w1t)[i] = f2tf4(W1[i]);
        ((float4*)g_w2t)[i] = f2tf4(W2[i]);
    }
}

__global__ void hist_k(const int* __restrict__ dst, int E) {
    for (int e = blockIdx.x * blockDim.x + threadIdx.x; e < E;
         e += gridDim.x * blockDim.x)
        atomicAdd(&g_cnt[dst[e]], 1);
}

// Coalesced block-local exclusive scan (1024/block)
__global__ void scan1_k(int N) {
    __shared__ int sh[1024];
    int t = threadIdx.x;
    int i = blockIdx.x * 1024 + t;
    int c = (i < N) ? g_cnt[i] : 0;
    sh[t] = c;
    __syncthreads();
    #pragma unroll
    for (int off = 1; off < 1024; off <<= 1) {
        int v = (t >= off) ? sh[t - off] : 0;
        __syncthreads();
        sh[t] += v;
        __syncthreads();
    }
    if (i < N) g_offs[i] = sh[t] - c;     // exclusive, block-local
    if (t == 1023) g_bsum[blockIdx.x] = sh[1023];
}

// Fixup: each block scans the <=64 block sums in smem, then applies prefix.
__global__ void scan3_k(int N, int E, int B1) {
    __shared__ int bs[64];
    int t = threadIdx.x;
    if (t < 64) bs[t] = (t < B1) ? g_bsum[t] : 0;
    __syncthreads();
    #pragma unroll
    for (int off = 1; off < 64; off <<= 1) {
        int v = 0;
        if (t < 64 && t >= off) v = bs[t - off];
        __syncthreads();
        if (t < 64) bs[t] += v;           // inclusive scan
        __syncthreads();
    }
    int i = blockIdx.x * blockDim.x + t;
    if (i < N) {
        int k = i >> 10;
        int pre = (k == 0) ? 0 : bs[k - 1];
        int o = g_offs[i] + pre;
        g_offs[i] = o;
        g_cnt[i]  = o;                    // cursor for placement
    }
    if (i == 0) g_offs[N] = E;
}

// Counting-sort placement: one 8B store per edge (src, weight packed)
__global__ void place_k(const int* __restrict__ src,
                        const int* __restrict__ dst,
                        const float* __restrict__ ew, int E) {
    for (int e = blockIdx.x * blockDim.x + threadIdx.x; e < E;
         e += gridDim.x * blockDim.x) {
        int idx = atomicAdd(&g_cnt[dst[e]], 1);
        g_es[idx] = make_int2(src[e], __float_as_int(ew[e]));
    }
}

// Segmented gather-reduce: one warp per dst node.
// Stores tf32-ROUNDED bits into g_y.
__global__ void gather_k(const float4* __restrict__ x4,
                         const float* __restrict__ eps, int N) {
    int gt = blockIdx.x * blockDim.x + threadIdx.x;
    int d = gt >> 5;
    if (d >= N) return;
    int lane = gt & 31;

    float s1 = 1.0f + eps[0];
    float4 acc = x4[(long)d * F4 + lane];
    acc.x *= s1; acc.y *= s1; acc.z *= s1; acc.w *= s1;

    int i   = g_offs[d];
    int end = g_offs[d + 1];

    for (; i + 4 <= end; i += 4) {
        int2 e0 = g_es[i],     e1 = g_es[i + 1];
        int2 e2 = g_es[i + 2], e3 = g_es[i + 3];
        float w0 = __int_as_float(e0.y), w1 = __int_as_float(e1.y);
        float w2 = __int_as_float(e2.y), w3 = __int_as_float(e3.y);
        float4 v0 = x4[(long)e0.x * F4 + lane];
        float4 v1 = x4[(long)e1.x * F4 + lane];
        float4 v2 = x4[(long)e2.x * F4 + lane];
        float4 v3 = x4[(long)e3.x * F4 + lane];
        acc.x = fmaf(w0, v0.x, acc.x); acc.y = fmaf(w0, v0.y, acc.y);
        acc.z = fmaf(w0, v0.z, acc.z); acc.w = fmaf(w0, v0.w, acc.w);
        acc.x = fmaf(w1, v1.x, acc.x); acc.y = fmaf(w1, v1.y, acc.y);
        acc.z = fmaf(w1, v1.z, acc.z); acc.w = fmaf(w1, v1.w, acc.w);
        acc.x = fmaf(w2, v2.x, acc.x); acc.y = fmaf(w2, v2.y, acc.y);
        acc.z = fmaf(w2, v2.z, acc.z); acc.w = fmaf(w2, v2.w, acc.w);
        acc.x = fmaf(w3, v3.x, acc.x); acc.y = fmaf(w3, v3.y, acc.y);
        acc.z = fmaf(w3, v3.z, acc.z); acc.w = fmaf(w3, v3.w, acc.w);
    }
    for (; i < end; i++) {
        int2 e0 = g_es[i];
        float w = __int_as_float(e0.y);
        float4 v = x4[(long)e0.x * F4 + lane];
        acc.x = fmaf(w, v.x, acc.x); acc.y = fmaf(w, v.y, acc.y);
        acc.z = fmaf(w, v.z, acc.z); acc.w = fmaf(w, v.w, acc.w);
    }
    ((float4*)g_y)[(long)d * F4 + lane] = f2tf4(acc);
}

// ---------------------------------------------------------------------------
__device__ __forceinline__ void mma_tf32(float c[4],
                                         unsigned a0, unsigned a1,
                                         unsigned a2, unsigned a3,
                                         unsigned b0, unsigned b1) {
    asm volatile(
        "mma.sync.aligned.m16n8k8.row.col.f32.tf32.tf32.f32 "
        "{%0,%1,%2,%3}, {%4,%5,%6,%7}, {%8,%9}, {%0,%1,%2,%3};"
        : "+f"(c[0]), "+f"(c[1]), "+f"(c[2]), "+f"(c[3])
        : "r"(a0), "r"(a1), "r"(a2), "r"(a3), "r"(b0), "r"(b1));
}

// ---------------------------------------------------------------------------
// Fused tf32 tensor-core MLP — 512 threads, 16 warps.
// Staging is pure float4 copies (W pre-converted, y pre-rounded).
__global__ void __launch_bounds__(512, 2)
gemm_tc(const float* __restrict__ b1, const float* __restrict__ b2,
        float4* __restrict__ out4, int N) {
    extern __shared__ float smem[];
    float* ysm = smem;                    // TROW x PAD
    float* wsm = smem + TROW * PAD;       // F x PAD

    int tid  = threadIdx.x;
    int lane = tid & 31;
    int w    = tid >> 5;                  // 0..15
    int g    = lane >> 2;                 // 0..7
    int tig  = lane & 3;                  // 0..3
    int f0   = (w & 7) * 16;              // feature base
    int nb   = (w >> 3) * 32;             // node base (0 or 32)
    int row0 = blockIdx.x * TROW;

    // ---- Stage W1 and y tile (pure float4 copies) ----
    for (int i = tid; i < F * F4; i += 512) {
        int k = i >> 5, c = i & 31;
        ((float4*)(wsm + k * PAD))[c] = ((const float4*)g_w1t)[i];
    }
    for (int i = tid; i < TROW * F4; i += 512) {
        int r = i >> 5, c = i & 31;
        int gr = row0 + r;
        float4 v = (gr < N) ? ((const float4*)g_y)[(long)gr * F4 + c]
                            : make_float4(0.f, 0.f, 0.f, 0.f);
        ((float4*)(ysm + r * PAD))[c] = v;
    }
    __syncthreads();

    float acc[4][4];
    {
        float bl = b1[f0 + g], bh = b1[f0 + g + 8];
        #pragma unroll
        for (int nt = 0; nt < 4; nt++) {
            acc[nt][0] = bl; acc[nt][1] = bl; acc[nt][2] = bh; acc[nt][3] = bh;
        }
    }
    #pragma unroll
    for (int ks = 0; ks < 16; ks++) {
        int kb = ks * 8;
        unsigned a0 = __float_as_uint(wsm[(kb + tig)     * PAD + f0 + g]);
        unsigned a1 = __float_as_uint(wsm[(kb + tig)     * PAD + f0 + g + 8]);
        unsigned a2 = __float_as_uint(wsm[(kb + tig + 4) * PAD + f0 + g]);
        unsigned a3 = __float_as_uint(wsm[(kb + tig + 4) * PAD + f0 + g + 8]);
        #pragma unroll
        for (int nt = 0; nt < 4; nt++) {
            unsigned b0 = __float_as_uint(ysm[(nb + nt * 8 + g) * PAD + kb + tig]);
            unsigned b1r = __float_as_uint(ysm[(nb + nt * 8 + g) * PAD + kb + tig + 4]);
            mma_tf32(acc[nt], a0, a1, a2, a3, b0, b1r);
        }
    }
    #pragma unroll
    for (int nt = 0; nt < 4; nt++)
        #pragma unroll
        for (int j = 0; j < 4; j++)
            acc[nt][j] = fmaxf(acc[nt][j], 0.0f);

    __syncthreads();   // all reads of ysm/wsm done

    // ---- h1 (tf32) -> ysm; W2 -> wsm ----
    #pragma unroll
    for (int nt = 0; nt < 4; nt++) {
        int r0r = (nb + nt * 8 + 2 * tig) * PAD;
        int r1r = (nb + nt * 8 + 2 * tig + 1) * PAD;
        ysm[r0r + f0 + g]     = __uint_as_float(f2tf(acc[nt][0]));
        ysm[r1r + f0 + g]     = __uint_as_float(f2tf(acc[nt][1]));
        ysm[r0r + f0 + g + 8] = __uint_as_float(f2tf(acc[nt][2]));
        ysm[r1r + f0 + g + 8] = __uint_as_float(f2tf(acc[nt][3]));
    }
    for (int i = tid; i < F * F4; i += 512) {
        int k = i >> 5, c = i & 31;
        ((float4*)(wsm + k * PAD))[c] = ((const float4*)g_w2t)[i];
    }
    __syncthreads();

    {
        float bl = b2[f0 + g], bh = b2[f0 + g + 8];
        #pragma unroll
        for (int nt = 0; nt < 4; nt++) {
            acc[nt][0] = bl; acc[nt][1] = bl; acc[nt][2] = bh; acc[nt][3] = bh;
        }
    }
    #pragma unroll
    for (int ks = 0; ks < 16; ks++) {
        int kb = ks * 8;
        unsigned a0 = __float_as_uint(wsm[(kb + tig)     * PAD + f0 + g]);
        unsigned a1 = __float_as_uint(wsm[(kb + tig)     * PAD + f0 + g + 8]);
        unsigned a2 = __float_as_uint(wsm[(kb + tig + 4) * PAD + f0 + g]);
        unsigned a3 = __float_as_uint(wsm[(kb + tig + 4) * PAD + f0 + g + 8]);
        #pragma unroll
        for (int nt = 0; nt < 4; nt++) {
            unsigned b0 = __float_as_uint(ysm[(nb + nt * 8 + g) * PAD + kb + tig]);
            unsigned b1r = __float_as_uint(ysm[(nb + nt * 8 + g) * PAD + kb + tig + 4]);
            mma_tf32(acc[nt], a0, a1, a2, a3, b0, b1r);
        }
    }
    __syncthreads();   // all reads of ysm done

    // ---- h2 (full fp32) -> ysm[node][feat] for coalesced store ----
    #pragma unroll
    for (int nt = 0; nt < 4; nt++) {
        int r0r = (nb + nt * 8 + 2 * tig) * PAD;
        int r1r = (nb + nt * 8 + 2 * tig + 1) * PAD;
        ysm[r0r + f0 + g]     = acc[nt][0];
        ysm[r1r + f0 + g]     = acc[nt][1];
        ysm[r0r + f0 + g + 8] = acc[nt][2];
        ysm[r1r + f0 + g + 8] = acc[nt][3];
    }
    __syncthreads();

    // ---- Coalesced store + BN column partials (mask phantom rows) ----
    float cs[4] = {0.f, 0.f, 0.f, 0.f};
    float cq[4] = {0.f, 0.f, 0.f, 0.f};
    int c4 = tid & 31;
    int ty = tid >> 5;                    // 0..15
    #pragma unroll
    for (int j = 0; j < 4; j++) {
        int r = ty + j * 16;
        int gr = row0 + r;
        if (gr < N) {
            float4 v = ((const float4*)(ysm + r * PAD))[c4];
            out4[(long)gr * F4 + c4] = v;
            cs[0] += v.x; cs[1] += v.y; cs[2] += v.z; cs[3] += v.w;
            cq[0] += v.x * v.x; cq[1] += v.y * v.y;
            cq[2] += v.z * v.z; cq[3] += v.w * v.w;
        }
    }
    __syncthreads();   // done with ysm/wsm; reuse wsm for reduction
    #pragma unroll
    for (int j = 0; j < 4; j++) {
        wsm[ty * F + c4 * 4 + j]          = cs[j];
        wsm[16 * F + ty * F + c4 * 4 + j] = cq[j];
    }
    __syncthreads();
    if (tid < F) {
        float s = 0.f, q = 0.f;
        #pragma unroll
        for (int t = 0; t < 16; t++) {
            s += wsm[t * F + tid];
            q += wsm[16 * F + t * F + tid];
        }
        atomicAdd(&g_sum[tid], s);
        atomicAdd(&g_sumsq[tid], q);
    }
}

// ---------------------------------------------------------------------------
__global__ void bn_k(float4* __restrict__ out4,
                     const float4* __restrict__ gamma4,
                     const float4* __restrict__ beta4, int N) {
    float invN = 1.0f / (float)N;
    for (int i = blockIdx.x * blockDim.x + threadIdx.x; i < N * F4;
         i += gridDim.x * blockDim.x) {
        int c = i & 31;
        float4 s = ((const float4*)g_sum)[c];
        float4 q = ((const float4*)g_sumsq)[c];
        float4 g = gamma4[c];
        float4 b = beta4[c];
        float4 v = out4[i];

        float m, var, is;
        m = s.x * invN; var = q.x * invN - m * m; is = rsqrtf(var + 1e-5f);
        v.x = (v.x - m) * is * g.x + b.x;
        m = s.y * invN; var = q.y * invN - m * m; is = rsqrtf(var + 1e-5f);
        v.y = (v.y - m) * is * g.y + b.y;
        m = s.z * invN; var = q.z * invN - m * m; is = rsqrtf(var + 1e-5f);
        v.z = (v.z - m) * is * g.z + b.z;
        m = s.w * invN; var = q.w * invN - m * m; is = rsqrtf(var + 1e-5f);
        v.w = (v.w - m) * is * g.w + b.w;

        out4[i] = v;
    }
}

// ---------------------------------------------------------------------------
extern "C" void kernel_launch(void* const* d_in, const int* in_sizes, int n_in,
                              void* d_out, int out_size) {
    const float* x     = (const float*)d_in[0];
    const float* ew    = (const float*)d_in[1];
    const float* W1    = (const float*)d_in[2];
    const float* b1    = (const float*)d_in[3];
    const float* W2    = (const float*)d_in[4];
    const float* b2    = (const float*)d_in[5];
    const float* eps   = (const float*)d_in[6];
    const float* gamma = (const float*)d_in[7];
    const float* beta  = (const float*)d_in[8];
    const int*   src   = (const int*)d_in[9];
    const int*   dst   = (const int*)d_in[10];

    int N = in_sizes[0] / F;
    int E = in_sizes[1];
    float* out = (float*)d_out;

    int smem_bytes = (TROW * PAD + F * PAD) * (int)sizeof(float);
    cudaFuncSetAttribute(gemm_tc, cudaFuncAttributeMaxDynamicSharedMemorySize,
                         smem_bytes);

    int B1 = (N + 1023) / 1024;

    setup_k<<<(N + 255) / 256, 256>>>((const float4*)W1, (const float4*)W2, N);
    hist_k<<<1184, 256>>>(dst, E);
    scan1_k<<<B1, 1024>>>(N);
    scan3_k<<<(N + 255) / 256, 256>>>(N, E, B1);
    place_k<<<1184, 256>>>(src, dst, ew, E);
    gather_k<<<(N * 32 + 255) / 256, 256>>>((const float4*)x, eps, N);

    int nblk = (N + TROW - 1) / TROW;
    gemm_tc<<<nblk, 512, smem_bytes>>>(b1, b2, (float4*)out, N);

    bn_k<<<1184, 256>>>((float4*)out, (const float4*)gamma,
                        (const float4*)beta, N);
}

// round 11
// speedup vs baseline: 1.7193x; 1.0351x over previous
#include <cuda_runtime.h>

#define F     128
#define F4    32
#define NMAX  50000
#define EMAX  800000
#define TROW  64          // node rows per gemm block
#define PAD_Y 132         // ysm row pad: B-frag (4g+tig) + transpose stores conflict-free
#define PAD_W 136         // wsm row pad: A-frag (8tig+g) conflict-free

// Scratch (allocation-free rule: __device__ globals)
__device__ __align__(16) float g_y[NMAX * F];      // tf32-rounded aggregated feats
__device__ __align__(16) float g_w1t[F * F];       // tf32-rounded W1
__device__ __align__(16) float g_w2t[F * F];       // tf32-rounded W2
__device__ __align__(16) float g_sum[F];
__device__ __align__(16) float g_sumsq[F];
__device__ int   g_cnt[NMAX];                      // histogram, then cursor
__device__ int   g_offs[NMAX + 1];                 // segment offsets
__device__ int   g_bsum[64];                       // scan block sums
__device__ __align__(16) int2 g_es[EMAX];          // dst-sorted (src, w) pairs

// ---------------------------------------------------------------------------
__device__ __forceinline__ unsigned f2tf(float f) {
    unsigned u;
    asm("cvt.rna.tf32.f32 %0, %1;" : "=r"(u) : "f"(f));
    return u;
}
__device__ __forceinline__ float4 f2tf4(float4 v) {
    return make_float4(__uint_as_float(f2tf(v.x)), __uint_as_float(f2tf(v.y)),
                       __uint_as_float(f2tf(v.z)), __uint_as_float(f2tf(v.w)));
}

// Setup: zero counters/stats + one-time tf32 conversion of W1, W2
__global__ void setup_k(const float4* __restrict__ W1,
                        const float4* __restrict__ W2, int N) {
    int i = blockIdx.x * blockDim.x + threadIdx.x;
    if (i < N) g_cnt[i] = 0;
    if (i < F) { g_sum[i] = 0.0f; g_sumsq[i] = 0.0f; }
    if (i < F * F4) {
        ((float4*)g_w1t)[i] = f2tf4(W1[i]);
        ((float4*)g_w2t)[i] = f2tf4(W2[i]);
    }
}

__global__ void hist_k(const int* __restrict__ dst, int E) {
    for (int e = blockIdx.x * blockDim.x + threadIdx.x; e < E;
         e += gridDim.x * blockDim.x)
        atomicAdd(&g_cnt[dst[e]], 1);
}

// Coalesced block-local exclusive scan (1024/block)
__global__ void scan1_k(int N) {
    __shared__ int sh[1024];
    int t = threadIdx.x;
    int i = blockIdx.x * 1024 + t;
    int c = (i < N) ? g_cnt[i] : 0;
    sh[t] = c;
    __syncthreads();
    #pragma unroll
    for (int off = 1; off < 1024; off <<= 1) {
        int v = (t >= off) ? sh[t - off] : 0;
        __syncthreads();
        sh[t] += v;
        __syncthreads();
    }
    if (i < N) g_offs[i] = sh[t] - c;     // exclusive, block-local
    if (t == 1023) g_bsum[blockIdx.x] = sh[1023];
}

// Fixup: each block scans the <=64 block sums in smem, then applies prefix.
__global__ void scan3_k(int N, int E, int B1) {
    __shared__ int bs[64];
    int t = threadIdx.x;
    if (t < 64) bs[t] = (t < B1) ? g_bsum[t] : 0;
    __syncthreads();
    #pragma unroll
    for (int off = 1; off < 64; off <<= 1) {
        int v = 0;
        if (t < 64 && t >= off) v = bs[t - off];
        __syncthreads();
        if (t < 64) bs[t] += v;           // inclusive scan
        __syncthreads();
    }
    int i = blockIdx.x * blockDim.x + t;
    if (i < N) {
        int k = i >> 10;
        int pre = (k == 0) ? 0 : bs[k - 1];
        int o = g_offs[i] + pre;
        g_offs[i] = o;
        g_cnt[i]  = o;                    // cursor for placement
    }
    if (i == 0) g_offs[N] = E;
}

// Counting-sort placement: one 8B store per edge (src, weight packed)
__global__ void place_k(const int* __restrict__ src,
                        const int* __restrict__ dst,
                        const float* __restrict__ ew, int E) {
    for (int e = blockIdx.x * blockDim.x + threadIdx.x; e < E;
         e += gridDim.x * blockDim.x) {
        int idx = atomicAdd(&g_cnt[dst[e]], 1);
        g_es[idx] = make_int2(src[e], __float_as_int(ew[e]));
    }
}

// Segmented gather-reduce: one warp per dst node.
// Stores tf32-ROUNDED bits into g_y.
__global__ void gather_k(const float4* __restrict__ x4,
                         const float* __restrict__ eps, int N) {
    int gt = blockIdx.x * blockDim.x + threadIdx.x;
    int d = gt >> 5;
    if (d >= N) return;
    int lane = gt & 31;

    float s1 = 1.0f + eps[0];
    float4 acc = x4[(long)d * F4 + lane];
    acc.x *= s1; acc.y *= s1; acc.z *= s1; acc.w *= s1;

    int i   = g_offs[d];
    int end = g_offs[d + 1];

    for (; i + 4 <= end; i += 4) {
        int2 e0 = g_es[i],     e1 = g_es[i + 1];
        int2 e2 = g_es[i + 2], e3 = g_es[i + 3];
        float w0 = __int_as_float(e0.y), w1 = __int_as_float(e1.y);
        float w2 = __int_as_float(e2.y), w3 = __int_as_float(e3.y);
        float4 v0 = x4[(long)e0.x * F4 + lane];
        float4 v1 = x4[(long)e1.x * F4 + lane];
        float4 v2 = x4[(long)e2.x * F4 + lane];
        float4 v3 = x4[(long)e3.x * F4 + lane];
        acc.x = fmaf(w0, v0.x, acc.x); acc.y = fmaf(w0, v0.y, acc.y);
        acc.z = fmaf(w0, v0.z, acc.z); acc.w = fmaf(w0, v0.w, acc.w);
        acc.x = fmaf(w1, v1.x, acc.x); acc.y = fmaf(w1, v1.y, acc.y);
        acc.z = fmaf(w1, v1.z, acc.z); acc.w = fmaf(w1, v1.w, acc.w);
        acc.x = fmaf(w2, v2.x, acc.x); acc.y = fmaf(w2, v2.y, acc.y);
        acc.z = fmaf(w2, v2.z, acc.z); acc.w = fmaf(w2, v2.w, acc.w);
        acc.x = fmaf(w3, v3.x, acc.x); acc.y = fmaf(w3, v3.y, acc.y);
        acc.z = fmaf(w3, v3.z, acc.z); acc.w = fmaf(w3, v3.w, acc.w);
    }
    for (; i < end; i++) {
        int2 e0 = g_es[i];
        float w = __int_as_float(e0.y);
        float4 v = x4[(long)e0.x * F4 + lane];
        acc.x = fmaf(w, v.x, acc.x); acc.y = fmaf(w, v.y, acc.y);
        acc.z = fmaf(w, v.z, acc.z); acc.w = fmaf(w, v.w, acc.w);
    }
    ((float4*)g_y)[(long)d * F4 + lane] = f2tf4(acc);
}

// ---------------------------------------------------------------------------
__device__ __forceinline__ void mma_tf32(float c[4],
                                         unsigned a0, unsigned a1,
                                         unsigned a2, unsigned a3,
                                         unsigned b0, unsigned b1) {
    asm volatile(
        "mma.sync.aligned.m16n8k8.row.col.f32.tf32.tf32.f32 "
        "{%0,%1,%2,%3}, {%4,%5,%6,%7}, {%8,%9}, {%0,%1,%2,%3};"
        : "+f"(c[0]), "+f"(c[1]), "+f"(c[2]), "+f"(c[3])
        : "r"(a0), "r"(a1), "r"(a2), "r"(a3), "r"(b0), "r"(b1));
}

// ---------------------------------------------------------------------------
// Fused tf32 tensor-core MLP — 512 threads, 16 warps.
// Dual-pad smem: ysm rows PAD_Y=132 (B frag + transpose conflict-free),
//                wsm rows PAD_W=136 (A frag conflict-free).
__global__ void __launch_bounds__(512, 2)
gemm_tc(const float* __restrict__ b1, const float* __restrict__ b2,
        float4* __restrict__ out4, int N) {
    extern __shared__ float smem[];
    float* ysm = smem;                        // TROW x PAD_Y
    float* wsm = smem + TROW * PAD_Y;         // F x PAD_W

    int tid  = threadIdx.x;
    int lane = tid & 31;
    int w    = tid >> 5;                  // 0..15
    int g    = lane >> 2;                 // 0..7
    int tig  = lane & 3;                  // 0..3
    int f0   = (w & 7) * 16;              // feature base
    int nb   = (w >> 3) * 32;             // node base (0 or 32)
    int row0 = blockIdx.x * TROW;

    // ---- Stage W1 and y tile (pure float4 copies) ----
    for (int i = tid; i < F * F4; i += 512) {
        int k = i >> 5, c = i & 31;
        ((float4*)(wsm + k * PAD_W))[c] = ((const float4*)g_w1t)[i];
    }
    for (int i = tid; i < TROW * F4; i += 512) {
        int r = i >> 5, c = i & 31;
        int gr = row0 + r;
        float4 v = (gr < N) ? ((const float4*)g_y)[(long)gr * F4 + c]
                            : make_float4(0.f, 0.f, 0.f, 0.f);
        ((float4*)(ysm + r * PAD_Y))[c] = v;
    }
    __syncthreads();

    float acc[4][4];
    {
        float bl = b1[f0 + g], bh = b1[f0 + g + 8];
        #pragma unroll
        for (int nt = 0; nt < 4; nt++) {
            acc[nt][0] = bl; acc[nt][1] = bl; acc[nt][2] = bh; acc[nt][3] = bh;
        }
    }
    #pragma unroll
    for (int ks = 0; ks < 16; ks++) {
        int kb = ks * 8;
        unsigned a0 = __float_as_uint(wsm[(kb + tig)     * PAD_W + f0 + g]);
        unsigned a1 = __float_as_uint(wsm[(kb + tig)     * PAD_W + f0 + g + 8]);
        unsigned a2 = __float_as_uint(wsm[(kb + tig + 4) * PAD_W + f0 + g]);
        unsigned a3 = __float_as_uint(wsm[(kb + tig + 4) * PAD_W + f0 + g + 8]);
        #pragma unroll
        for (int nt = 0; nt < 4; nt++) {
            unsigned b0 = __float_as_uint(ysm[(nb + nt * 8 + g) * PAD_Y + kb + tig]);
            unsigned b1r = __float_as_uint(ysm[(nb + nt * 8 + g) * PAD_Y + kb + tig + 4]);
            mma_tf32(acc[nt], a0, a1, a2, a3, b0, b1r);
        }
    }
    #pragma unroll
    for (int nt = 0; nt < 4; nt++)
        #pragma unroll
        for (int j = 0; j < 4; j++)
            acc[nt][j] = fmaxf(acc[nt][j], 0.0f);

    __syncthreads();   // all reads of ysm/wsm done

    // ---- h1 (tf32) -> ysm; W2 -> wsm ----
    #pragma unroll
    for (int nt = 0; nt < 4; nt++) {
        int r0r = (nb + nt * 8 + 2 * tig) * PAD_Y;
        int r1r = (nb + nt * 8 + 2 * tig + 1) * PAD_Y;
        ysm[r0r + f0 + g]     = __uint_as_float(f2tf(acc[nt][0]));
        ysm[r1r + f0 + g]     = __uint_as_float(f2tf(acc[nt][1]));
        ysm[r0r + f0 + g + 8] = __uint_as_float(f2tf(acc[nt][2]));
        ysm[r1r + f0 + g + 8] = __uint_as_float(f2tf(acc[nt][3]));
    }
    for (int i = tid; i < F * F4; i += 512) {
        int k = i >> 5, c = i & 31;
        ((float4*)(wsm + k * PAD_W))[c] = ((const float4*)g_w2t)[i];
    }
    __syncthreads();

    {
        float bl = b2[f0 + g], bh = b2[f0 + g + 8];
        #pragma unroll
        for (int nt = 0; nt < 4; nt++) {
            acc[nt][0] = bl; acc[nt][1] = bl; acc[nt][2] = bh; acc[nt][3] = bh;
        }
    }
    #pragma unroll
    for (int ks = 0; ks < 16; ks++) {
        int kb = ks * 8;
        unsigned a0 = __float_as_uint(wsm[(kb + tig)     * PAD_W + f0 + g]);
        unsigned a1 = __float_as_uint(wsm[(kb + tig)     * PAD_W + f0 + g + 8]);
        unsigned a2 = __float_as_uint(wsm[(kb + tig + 4) * PAD_W + f0 + g]);
        unsigned a3 = __float_as_uint(wsm[(kb + tig + 4) * PAD_W + f0 + g + 8]);
        #pragma unroll
        for (int nt = 0; nt < 4; nt++) {
            unsigned b0 = __float_as_uint(ysm[(nb + nt * 8 + g) * PAD_Y + kb + tig]);
            unsigned b1r = __float_as_uint(ysm[(nb + nt * 8 + g) * PAD_Y + kb + tig + 4]);
            mma_tf32(acc[nt], a0, a1, a2, a3, b0, b1r);
        }
    }
    __syncthreads();   // all reads of ysm done

    // ---- h2 (full fp32) -> ysm[node][feat] for coalesced store ----
    #pragma unroll
    for (int nt = 0; nt < 4; nt++) {
        int r0r = (nb + nt * 8 + 2 * tig) * PAD_Y;
        int r1r = (nb + nt * 8 + 2 * tig + 1) * PAD_Y;
        ysm[r0r + f0 + g]     = acc[nt][0];
        ysm[r1r + f0 + g]     = acc[nt][1];
        ysm[r0r + f0 + g + 8] = acc[nt][2];
        ysm[r1r + f0 + g + 8] = acc[nt][3];
    }
    __syncthreads();

    // ---- Coalesced store + BN column partials (mask phantom rows) ----
    float cs[4] = {0.f, 0.f, 0.f, 0.f};
    float cq[4] = {0.f, 0.f, 0.f, 0.f};
    int c4 = tid & 31;
    int ty = tid >> 5;                    // 0..15
    #pragma unroll
    for (int j = 0; j < 4; j++) {
        int r = ty + j * 16;
        int gr = row0 + r;
        if (gr < N) {
            float4 v = ((const float4*)(ysm + r * PAD_Y))[c4];
            out4[(long)gr * F4 + c4] = v;
            cs[0] += v.x; cs[1] += v.y; cs[2] += v.z; cs[3] += v.w;
            cq[0] += v.x * v.x; cq[1] += v.y * v.y;
            cq[2] += v.z * v.z; cq[3] += v.w * v.w;
        }
    }
    __syncthreads();   // done with ysm/wsm; reuse wsm for reduction
    #pragma unroll
    for (int j = 0; j < 4; j++) {
        wsm[ty * F + c4 * 4 + j]          = cs[j];
        wsm[16 * F + ty * F + c4 * 4 + j] = cq[j];
    }
    __syncthreads();
    if (tid < F) {
        float s = 0.f, q = 0.f;
        #pragma unroll
        for (int t = 0; t < 16; t++) {
            s += wsm[t * F + tid];
            q += wsm[16 * F + t * F + tid];
        }
        atomicAdd(&g_sum[tid], s);
        atomicAdd(&g_sumsq[tid], q);
    }
}

// ---------------------------------------------------------------------------
__global__ void bn_k(float4* __restrict__ out4,
                     const float4* __restrict__ gamma4,
                     const float4* __restrict__ beta4, int N) {
    float invN = 1.0f / (float)N;
    for (int i = blockIdx.x * blockDim.x + threadIdx.x; i < N * F4;
         i += gridDim.x * blockDim.x) {
        int c = i & 31;
        float4 s = ((const float4*)g_sum)[c];
        float4 q = ((const float4*)g_sumsq)[c];
        float4 g = gamma4[c];
        float4 b = beta4[c];
        float4 v = out4[i];

        float m, var, is;
        m = s.x * invN; var = q.x * invN - m * m; is = rsqrtf(var + 1e-5f);
        v.x = (v.x - m) * is * g.x + b.x;
        m = s.y * invN; var = q.y * invN - m * m; is = rsqrtf(var + 1e-5f);
        v.y = (v.y - m) * is * g.y + b.y;
        m = s.z * invN; var = q.z * invN - m * m; is = rsqrtf(var + 1e-5f);
        v.z = (v.z - m) * is * g.z + b.z;
        m = s.w * invN; var = q.w * invN - m * m; is = rsqrtf(var + 1e-5f);
        v.w = (v.w - m) * is * g.w + b.w;

        out4[i] = v;
    }
}

// ---------------------------------------------------------------------------
extern "C" void kernel_launch(void* const* d_in, const int* in_sizes, int n_in,
                              void* d_out, int out_size) {
    const float* x     = (const float*)d_in[0];
    const float* ew    = (const float*)d_in[1];
    const float* W1    = (const float*)d_in[2];
    const float* b1    = (const float*)d_in[3];
    const float* W2    = (const float*)d_in[4];
    const float* b2    = (const float*)d_in[5];
    const float* eps   = (const float*)d_in[6];
    const float* gamma = (const float*)d_in[7];
    const float* beta  = (const float*)d_in[8];
    const int*   src   = (const int*)d_in[9];
    const int*   dst   = (const int*)d_in[10];

    int N = in_sizes[0] / F;
    int E = in_sizes[1];
    float* out = (float*)d_out;

    int smem_bytes = (TROW * PAD_Y + F * PAD_W) * (int)sizeof(float);
    cudaFuncSetAttribute(gemm_tc, cudaFuncAttributeMaxDynamicSharedMemorySize,
                         smem_bytes);

    int B1 = (N + 1023) / 1024;

    setup_k<<<(N + 255) / 256, 256>>>((const float4*)W1, (const float4*)W2, N);
    hist_k<<<1184, 256>>>(dst, E);
    scan1_k<<<B1, 1024>>>(N);
    scan3_k<<<(N + 255) / 256, 256>>>(N, E, B1);
    place_k<<<1184, 256>>>(src, dst, ew, E);
    gather_k<<<(N * 32 + 255) / 256, 256>>>((const float4*)x, eps, N);

    int nblk = (N + TROW - 1) / TROW;
    gemm_tc<<<nblk, 512, smem_bytes>>>(b1, b2, (float4*)out, N);

    bn_k<<<1184, 256>>>((float4*)out, (const float4*)gamma,
                        (const float4*)beta, N);
}

// round 14
// speedup vs baseline: 1.7823x; 1.0367x over previous
#include <cuda_runtime.h>

#define F     128
#define F4    32
#define NMAX  50000
#define EMAX  800000
#define TROW  64          // node rows per gemm tile
#define PAD_Y 132         // ysm row pad: B-frag (4g+tig) + transpose stores conflict-free
#define PAD_W 136         // wsm row pad: A-frag (8tig+g) conflict-free
#define GCTAS 148         // persistent gemm CTAs (1/SM)

// Scratch (allocation-free rule: __device__ globals)
__device__ __align__(16) float g_y[NMAX * F];      // tf32-rounded aggregated feats
__device__ __align__(16) float g_w1t[F * F];       // tf32-rounded W1
__device__ __align__(16) float g_w2t[F * F];       // tf32-rounded W2
__device__ __align__(16) float g_sum[F];
__device__ __align__(16) float g_sumsq[F];
__device__ int   g_cnt[NMAX];                      // histogram, then cursor
__device__ int   g_offs[NMAX + 1];                 // segment offsets
__device__ int   g_bsum[64];                       // scan block sums
__device__ __align__(16) int2 g_es[EMAX];          // dst-sorted (src, w) pairs

// ---------------------------------------------------------------------------
__device__ __forceinline__ unsigned f2tf(float f) {
    unsigned u;
    asm("cvt.rna.tf32.f32 %0, %1;" : "=r"(u) : "f"(f));
    return u;
}
__device__ __forceinline__ float4 f2tf4(float4 v) {
    return make_float4(__uint_as_float(f2tf(v.x)), __uint_as_float(f2tf(v.y)),
                       __uint_as_float(f2tf(v.z)), __uint_as_float(f2tf(v.w)));
}

// Setup: zero counters/stats + one-time tf32 conversion of W1, W2
__global__ void setup_k(const float4* __restrict__ W1,
                        const float4* __restrict__ W2, int N) {
    int i = blockIdx.x * blockDim.x + threadIdx.x;
    if (i < N) g_cnt[i] = 0;
    if (i < F) { g_sum[i] = 0.0f; g_sumsq[i] = 0.0f; }
    if (i < F * F4) {
        ((float4*)g_w1t)[i] = f2tf4(W1[i]);
        ((float4*)g_w2t)[i] = f2tf4(W2[i]);
    }
}

__global__ void hist_k(const int* __restrict__ dst, int E) {
    for (int e = blockIdx.x * blockDim.x + threadIdx.x; e < E;
         e += gridDim.x * blockDim.x)
        atomicAdd(&g_cnt[dst[e]], 1);
}

// Coalesced block-local exclusive scan (1024/block)
__global__ void scan1_k(int N) {
    __shared__ int sh[1024];
    int t = threadIdx.x;
    int i = blockIdx.x * 1024 + t;
    int c = (i < N) ? g_cnt[i] : 0;
    sh[t] = c;
    __syncthreads();
    #pragma unroll
    for (int off = 1; off < 1024; off <<= 1) {
        int v = (t >= off) ? sh[t - off] : 0;
        __syncthreads();
        sh[t] += v;
        __syncthreads();
    }
    if (i < N) g_offs[i] = sh[t] - c;     // exclusive, block-local
    if (t == 1023) g_bsum[blockIdx.x] = sh[1023];
}

// Fixup: each block scans the <=64 block sums in smem, then applies prefix.
__global__ void scan3_k(int N, int E, int B1) {
    __shared__ int bs[64];
    int t = threadIdx.x;
    if (t < 64) bs[t] = (t < B1) ? g_bsum[t] : 0;
    __syncthreads();
    #pragma unroll
    for (int off = 1; off < 64; off <<= 1) {
        int v = 0;
        if (t < 64 && t >= off) v = bs[t - off];
        __syncthreads();
        if (t < 64) bs[t] += v;           // inclusive scan
        __syncthreads();
    }
    int i = blockIdx.x * blockDim.x + t;
    if (i < N) {
        int k = i >> 10;
        int pre = (k == 0) ? 0 : bs[k - 1];
        int o = g_offs[i] + pre;
        g_offs[i] = o;
        g_cnt[i]  = o;                    // cursor for placement
    }
    if (i == 0) g_offs[N] = E;
}

// Counting-sort placement: one 8B store per edge (src, weight packed)
__global__ void place_k(const int* __restrict__ src,
                        const int* __restrict__ dst,
                        const float* __restrict__ ew, int E) {
    for (int e = blockIdx.x * blockDim.x + threadIdx.x; e < E;
         e += gridDim.x * blockDim.x) {
        int idx = atomicAdd(&g_cnt[dst[e]], 1);
        g_es[idx] = make_int2(src[e], __float_as_int(ew[e]));
    }
}

// Segmented gather-reduce: one warp per dst node.
// Stores tf32-ROUNDED bits into g_y.
__global__ void gather_k(const float4* __restrict__ x4,
                         const float* __restrict__ eps, int N) {
    int gt = blockIdx.x * blockDim.x + threadIdx.x;
    int d = gt >> 5;
    if (d >= N) return;
    int lane = gt & 31;

    float s1 = 1.0f + eps[0];
    float4 acc = x4[(long)d * F4 + lane];
    acc.x *= s1; acc.y *= s1; acc.z *= s1; acc.w *= s1;

    int i   = g_offs[d];
    int end = g_offs[d + 1];

    for (; i + 4 <= end; i += 4) {
        int2 e0 = g_es[i],     e1 = g_es[i + 1];
        int2 e2 = g_es[i + 2], e3 = g_es[i + 3];
        float w0 = __int_as_float(e0.y), w1 = __int_as_float(e1.y);
        float w2 = __int_as_float(e2.y), w3 = __int_as_float(e3.y);
        float4 v0 = x4[(long)e0.x * F4 + lane];
        float4 v1 = x4[(long)e1.x * F4 + lane];
        float4 v2 = x4[(long)e2.x * F4 + lane];
        float4 v3 = x4[(long)e3.x * F4 + lane];
        acc.x = fmaf(w0, v0.x, acc.x); acc.y = fmaf(w0, v0.y, acc.y);
        acc.z = fmaf(w0, v0.z, acc.z); acc.w = fmaf(w0, v0.w, acc.w);
        acc.x = fmaf(w1, v1.x, acc.x); acc.y = fmaf(w1, v1.y, acc.y);
        acc.z = fmaf(w1, v1.z, acc.z); acc.w = fmaf(w1, v1.w, acc.w);
        acc.x = fmaf(w2, v2.x, acc.x); acc.y = fmaf(w2, v2.y, acc.y);
        acc.z = fmaf(w2, v2.z, acc.z); acc.w = fmaf(w2, v2.w, acc.w);
        acc.x = fmaf(w3, v3.x, acc.x); acc.y = fmaf(w3, v3.y, acc.y);
        acc.z = fmaf(w3, v3.z, acc.z); acc.w = fmaf(w3, v3.w, acc.w);
    }
    for (; i < end; i++) {
        int2 e0 = g_es[i];
        float w = __int_as_float(e0.y);
        float4 v = x4[(long)e0.x * F4 + lane];
        acc.x = fmaf(w, v.x, acc.x); acc.y = fmaf(w, v.y, acc.y);
        acc.z = fmaf(w, v.z, acc.z); acc.w = fmaf(w, v.w, acc.w);
    }
    ((float4*)g_y)[(long)d * F4 + lane] = f2tf4(acc);
}

// ---------------------------------------------------------------------------
__device__ __forceinline__ void mma_tf32(float c[4],
                                         unsigned a0, unsigned a1,
                                         unsigned a2, unsigned a3,
                                         unsigned b0, unsigned b1) {
    asm volatile(
        "mma.sync.aligned.m16n8k8.row.col.f32.tf32.tf32.f32 "
        "{%0,%1,%2,%3}, {%4,%5,%6,%7}, {%8,%9}, {%0,%1,%2,%3};"
        : "+f"(c[0]), "+f"(c[1]), "+f"(c[2]), "+f"(c[3])
        : "r"(a0), "r"(a1), "r"(a2), "r"(a3), "r"(b0), "r"(b1));
}

// ---------------------------------------------------------------------------
// Persistent fused tf32 tensor-core MLP — 148 CTAs x 512 threads, 1 CTA/SM.
// W1 AND W2 stay resident in smem for the whole kernel; each CTA loops tiles.
// smem: ysm 64xPAD_Y + w1sm 128xPAD_W + w2sm 128xPAD_W = ~173 KB.
__global__ void __launch_bounds__(512, 1)
gemm_tc(const float* __restrict__ b1, const float* __restrict__ b2,
        float4* __restrict__ out4, int N, int nTiles) {
    extern __shared__ float smem[];
    float* ysm  = smem;                         // TROW x PAD_Y
    float* w1sm = smem + TROW * PAD_Y;          // F x PAD_W
    float* w2sm = w1sm + F * PAD_W;             // F x PAD_W

    int tid  = threadIdx.x;
    int lane = tid & 31;
    int w    = tid >> 5;                  // 0..15
    int g    = lane >> 2;                 // 0..7
    int tig  = lane & 3;                  // 0..3
    int f0   = (w & 7) * 16;              // feature base
    int nb   = (w >> 3) * 32;             // node base (0 or 32)

    // ---- Stage W1 and W2 once ----
    for (int i = tid; i < F * F4; i += 512) {
        int k = i >> 5, c = i & 31;
        ((float4*)(w1sm + k * PAD_W))[c] = ((const float4*)g_w1t)[i];
        ((float4*)(w2sm + k * PAD_W))[c] = ((const float4*)g_w2t)[i];
    }

    // Hoisted biases
    float bl1 = b1[f0 + g], bh1 = b1[f0 + g + 8];
    float bl2 = b2[f0 + g], bh2 = b2[f0 + g + 8];

    // BN partials accumulated across tiles in registers
    float csA[4] = {0.f, 0.f, 0.f, 0.f};
    float cqA[4] = {0.f, 0.f, 0.f, 0.f};
    int c4 = tid & 31;
    int ty = tid >> 5;                    // 0..15

    for (int tile = blockIdx.x; tile < nTiles; tile += gridDim.x) {
        int row0 = tile * TROW;

        __syncthreads();   // prior tile's ysm reads complete before overwrite
        for (int i = tid; i < TROW * F4; i += 512) {
            int r = i >> 5, c = i & 31;
            int gr = row0 + r;
            float4 v = (gr < N) ? ((const float4*)g_y)[(long)gr * F4 + c]
                                : make_float4(0.f, 0.f, 0.f, 0.f);
            ((float4*)(ysm + r * PAD_Y))[c] = v;
        }
        __syncthreads();

        // ---- GEMM1 (w1sm) + ReLU ----
        float acc[4][4];
        #pragma unroll
        for (int nt = 0; nt < 4; nt++) {
            acc[nt][0] = bl1; acc[nt][1] = bl1; acc[nt][2] = bh1; acc[nt][3] = bh1;
        }
        #pragma unroll
        for (int ks = 0; ks < 16; ks++) {
            int kb = ks * 8;
            unsigned a0 = __float_as_uint(w1sm[(kb + tig)     * PAD_W + f0 + g]);
            unsigned a1 = __float_as_uint(w1sm[(kb + tig)     * PAD_W + f0 + g + 8]);
            unsigned a2 = __float_as_uint(w1sm[(kb + tig + 4) * PAD_W + f0 + g]);
            unsigned a3 = __float_as_uint(w1sm[(kb + tig + 4) * PAD_W + f0 + g + 8]);
            #pragma unroll
            for (int nt = 0; nt < 4; nt++) {
                unsigned b0 = __float_as_uint(ysm[(nb + nt * 8 + g) * PAD_Y + kb + tig]);
                unsigned b1r = __float_as_uint(ysm[(nb + nt * 8 + g) * PAD_Y + kb + tig + 4]);
                mma_tf32(acc[nt], a0, a1, a2, a3, b0, b1r);
            }
        }
        #pragma unroll
        for (int nt = 0; nt < 4; nt++)
            #pragma unroll
            for (int j = 0; j < 4; j++)
                acc[nt][j] = fmaxf(acc[nt][j], 0.0f);

        __syncthreads();   // all reads of ysm done

        // ---- h1 (tf32) -> ysm ----
        #pragma unroll
        for (int nt = 0; nt < 4; nt++) {
            int r0r = (nb + nt * 8 + 2 * tig) * PAD_Y;
            int r1r = (nb + nt * 8 + 2 * tig + 1) * PAD_Y;
            ysm[r0r + f0 + g]     = __uint_as_float(f2tf(acc[nt][0]));
            ysm[r1r + f0 + g]     = __uint_as_float(f2tf(acc[nt][1]));
            ysm[r0r + f0 + g + 8] = __uint_as_float(f2tf(acc[nt][2]));
            ysm[r1r + f0 + g + 8] = __uint_as_float(f2tf(acc[nt][3]));
        }
        __syncthreads();

        // ---- GEMM2 (w2sm) ----
        #pragma unroll
        for (int nt = 0; nt < 4; nt++) {
            acc[nt][0] = bl2; acc[nt][1] = bl2; acc[nt][2] = bh2; acc[nt][3] = bh2;
        }
        #pragma unroll
        for (int ks = 0; ks < 16; ks++) {
            int kb = ks * 8;
            unsigned a0 = __float_as_uint(w2sm[(kb + tig)     * PAD_W + f0 + g]);
            unsigned a1 = __float_as_uint(w2sm[(kb + tig)     * PAD_W + f0 + g + 8]);
            unsigned a2 = __float_as_uint(w2sm[(kb + tig + 4) * PAD_W + f0 + g]);
            unsigned a3 = __float_as_uint(w2sm[(kb + tig + 4) * PAD_W + f0 + g + 8]);
            #pragma unroll
            for (int nt = 0; nt < 4; nt++) {
                unsigned b0 = __float_as_uint(ysm[(nb + nt * 8 + g) * PAD_Y + kb + tig]);
                unsigned b1r = __float_as_uint(ysm[(nb + nt * 8 + g) * PAD_Y + kb + tig + 4]);
                mma_tf32(acc[nt], a0, a1, a2, a3, b0, b1r);
            }
        }
        __syncthreads();   // all reads of ysm done

        // ---- h2 (fp32) -> ysm for coalesced store ----
        #pragma unroll
        for (int nt = 0; nt < 4; nt++) {
            int r0r = (nb + nt * 8 + 2 * tig) * PAD_Y;
            int r1r = (nb + nt * 8 + 2 * tig + 1) * PAD_Y;
            ysm[r0r + f0 + g]     = acc[nt][0];
            ysm[r1r + f0 + g]     = acc[nt][1];
            ysm[r0r + f0 + g + 8] = acc[nt][2];
            ysm[r1r + f0 + g + 8] = acc[nt][3];
        }
        __syncthreads();

        // ---- Coalesced store + BN partial accumulate ----
        #pragma unroll
        for (int j = 0; j < 4; j++) {
            int r = ty + j * 16;
            int gr = row0 + r;
            if (gr < N) {
                float4 v = ((const float4*)(ysm + r * PAD_Y))[c4];
                out4[(long)gr * F4 + c4] = v;
                csA[0] += v.x; csA[1] += v.y; csA[2] += v.z; csA[3] += v.w;
                cqA[0] += v.x * v.x; cqA[1] += v.y * v.y;
                cqA[2] += v.z * v.z; cqA[3] += v.w * v.w;
            }
        }
    }

    // ---- One BN reduction per CTA ----
    __syncthreads();
    #pragma unroll
    for (int j = 0; j < 4; j++) {
        ysm[ty * F + c4 * 4 + j]          = csA[j];
        ysm[16 * F + ty * F + c4 * 4 + j] = cqA[j];
    }
    __syncthreads();
    if (tid < F) {
        float s = 0.f, q = 0.f;
        #pragma unroll
        for (int t = 0; t < 16; t++) {
            s += ysm[t * F + tid];
            q += ysm[16 * F + t * F + tid];
        }
        atomicAdd(&g_sum[tid], s);
        atomicAdd(&g_sumsq[tid], q);
    }
}

// ---------------------------------------------------------------------------
__global__ void bn_k(float4* __restrict__ out4,
                     const float4* __restrict__ gamma4,
                     const float4* __restrict__ beta4, int N) {
    float invN = 1.0f / (float)N;
    for (int i = blockIdx.x * blockDim.x + threadIdx.x; i < N * F4;
         i += gridDim.x * blockDim.x) {
        int c = i & 31;
        float4 s = ((const float4*)g_sum)[c];
        float4 q = ((const float4*)g_sumsq)[c];
        float4 g = gamma4[c];
        float4 b = beta4[c];
        float4 v = out4[i];

        float m, var, is;
        m = s.x * invN; var = q.x * invN - m * m; is = rsqrtf(var + 1e-5f);
        v.x = (v.x - m) * is * g.x + b.x;
        m = s.y * invN; var = q.y * invN - m * m; is = rsqrtf(var + 1e-5f);
        v.y = (v.y - m) * is * g.y + b.y;
        m = s.z * invN; var = q.z * invN - m * m; is = rsqrtf(var + 1e-5f);
        v.z = (v.z - m) * is * g.z + b.z;
        m = s.w * invN; var = q.w * invN - m * m; is = rsqrtf(var + 1e-5f);
        v.w = (v.w - m) * is * g.w + b.w;

        out4[i] = v;
    }
}

// ---------------------------------------------------------------------------
extern "C" void kernel_launch(void* const* d_in, const int* in_sizes, int n_in,
                              void* d_out, int out_size) {
    const float* x     = (const float*)d_in[0];
    const float* ew    = (const float*)d_in[1];
    const float* W1    = (const float*)d_in[2];
    const float* b1    = (const float*)d_in[3];
    const float* W2    = (const float*)d_in[4];
    const float* b2    = (const float*)d_in[5];
    const float* eps   = (const float*)d_in[6];
    const float* gamma = (const float*)d_in[7];
    const float* beta  = (const float*)d_in[8];
    const int*   src   = (const int*)d_in[9];
    const int*   dst   = (const int*)d_in[10];

    int N = in_sizes[0] / F;
    int E = in_sizes[1];
    float* out = (float*)d_out;

    int smem_bytes = (TROW * PAD_Y + 2 * F * PAD_W) * (int)sizeof(float);
    cudaFuncSetAttribute(gemm_tc, cudaFuncAttributeMaxDynamicSharedMemorySize,
                         smem_bytes);

    int B1 = (N + 1023) / 1024;

    setup_k<<<(N + 255) / 256, 256>>>((const float4*)W1, (const float4*)W2, N);
    hist_k<<<1184, 256>>>(dst, E);
    scan1_k<<<B1, 1024>>>(N);
    scan3_k<<<(N + 255) / 256, 256>>>(N, E, B1);
    place_k<<<1184, 256>>>(src, dst, ew, E);
    gather_k<<<(N * 32 + 255) / 256, 256>>>((const float4*)x, eps, N);

    int nTiles = (N + TROW - 1) / TROW;
    gemm_tc<<<GCTAS, 512, smem_bytes>>>(b1, b2, (float4*)out, N, nTiles);

    bn_k<<<1184, 256>>>((float4*)out, (const float4*)gamma,
                        (const float4*)beta, N);
}

// round 15
// speedup vs baseline: 1.8960x; 1.0638x over previous
#include <cuda_runtime.h>

#define F     128
#define F4    32
#define NMAX  50000
#define EMAX  800000
#define TROW  128         // node rows per gemm tile
#define PAD_Y 132         // ysm row pad: B-frag (4g+tig) + transpose stores conflict-free
#define PAD_W 136         // wsm row pad: A-frag (8tig+g) conflict-free
#define GCTAS 148         // persistent gemm CTAs (1/SM)

// Scratch (allocation-free rule: __device__ globals)
__device__ __align__(16) float g_y[NMAX * F];      // tf32-rounded aggregated feats
__device__ __align__(16) float g_w1t[F * F];       // tf32-rounded W1
__device__ __align__(16) float g_w2t[F * F];       // tf32-rounded W2
__device__ __align__(16) float g_sum[F];
__device__ __align__(16) float g_sumsq[F];
__device__ int   g_cnt[NMAX];                      // histogram, then cursor
__device__ int   g_offs[NMAX + 1];                 // segment offsets
__device__ int   g_bsum[64];                       // scan block sums
__device__ __align__(16) int2 g_es[EMAX];          // dst-sorted (src, w) pairs

// ---------------------------------------------------------------------------
__device__ __forceinline__ unsigned f2tf(float f) {
    unsigned u;
    asm("cvt.rna.tf32.f32 %0, %1;" : "=r"(u) : "f"(f));
    return u;
}
__device__ __forceinline__ float4 f2tf4(float4 v) {
    return make_float4(__uint_as_float(f2tf(v.x)), __uint_as_float(f2tf(v.y)),
                       __uint_as_float(f2tf(v.z)), __uint_as_float(f2tf(v.w)));
}

// Setup: zero counters/stats + one-time tf32 conversion of W1, W2
__global__ void setup_k(const float4* __restrict__ W1,
                        const float4* __restrict__ W2, int N) {
    int i = blockIdx.x * blockDim.x + threadIdx.x;
    if (i < N) g_cnt[i] = 0;
    if (i < F) { g_sum[i] = 0.0f; g_sumsq[i] = 0.0f; }
    if (i < F * F4) {
        ((float4*)g_w1t)[i] = f2tf4(W1[i]);
        ((float4*)g_w2t)[i] = f2tf4(W2[i]);
    }
}

__global__ void hist_k(const int* __restrict__ dst, int E) {
    for (int e = blockIdx.x * blockDim.x + threadIdx.x; e < E;
         e += gridDim.x * blockDim.x)
        atomicAdd(&g_cnt[dst[e]], 1);
}

// Coalesced block-local exclusive scan (1024/block)
__global__ void scan1_k(int N) {
    __shared__ int sh[1024];
    int t = threadIdx.x;
    int i = blockIdx.x * 1024 + t;
    int c = (i < N) ? g_cnt[i] : 0;
    sh[t] = c;
    __syncthreads();
    #pragma unroll
    for (int off = 1; off < 1024; off <<= 1) {
        int v = (t >= off) ? sh[t - off] : 0;
        __syncthreads();
        sh[t] += v;
        __syncthreads();
    }
    if (i < N) g_offs[i] = sh[t] - c;     // exclusive, block-local
    if (t == 1023) g_bsum[blockIdx.x] = sh[1023];
}

// Fixup: each block scans the <=64 block sums in smem, then applies prefix.
__global__ void scan3_k(int N, int E, int B1) {
    __shared__ int bs[64];
    int t = threadIdx.x;
    if (t < 64) bs[t] = (t < B1) ? g_bsum[t] : 0;
    __syncthreads();
    #pragma unroll
    for (int off = 1; off < 64; off <<= 1) {
        int v = 0;
        if (t < 64 && t >= off) v = bs[t - off];
        __syncthreads();
        if (t < 64) bs[t] += v;           // inclusive scan
        __syncthreads();
    }
    int i = blockIdx.x * blockDim.x + t;
    if (i < N) {
        int k = i >> 10;
        int pre = (k == 0) ? 0 : bs[k - 1];
        int o = g_offs[i] + pre;
        g_offs[i] = o;
        g_cnt[i]  = o;                    // cursor for placement
    }
    if (i == 0) g_offs[N] = E;
}

// Counting-sort placement: one 8B store per edge (src, weight packed)
__global__ void place_k(const int* __restrict__ src,
                        const int* __restrict__ dst,
                        const float* __restrict__ ew, int E) {
    for (int e = blockIdx.x * blockDim.x + threadIdx.x; e < E;
         e += gridDim.x * blockDim.x) {
        int idx = atomicAdd(&g_cnt[dst[e]], 1);
        g_es[idx] = make_int2(src[e], __float_as_int(ew[e]));
    }
}

// Segmented gather-reduce: one warp per dst node.
// Stores tf32-ROUNDED bits into g_y.
__global__ void gather_k(const float4* __restrict__ x4,
                         const float* __restrict__ eps, int N) {
    int gt = blockIdx.x * blockDim.x + threadIdx.x;
    int d = gt >> 5;
    if (d >= N) return;
    int lane = gt & 31;

    float s1 = 1.0f + eps[0];
    float4 acc = x4[(long)d * F4 + lane];
    acc.x *= s1; acc.y *= s1; acc.z *= s1; acc.w *= s1;

    int i   = g_offs[d];
    int end = g_offs[d + 1];

    for (; i + 4 <= end; i += 4) {
        int2 e0 = g_es[i],     e1 = g_es[i + 1];
        int2 e2 = g_es[i + 2], e3 = g_es[i + 3];
        float w0 = __int_as_float(e0.y), w1 = __int_as_float(e1.y);
        float w2 = __int_as_float(e2.y), w3 = __int_as_float(e3.y);
        float4 v0 = x4[(long)e0.x * F4 + lane];
        float4 v1 = x4[(long)e1.x * F4 + lane];
        float4 v2 = x4[(long)e2.x * F4 + lane];
        float4 v3 = x4[(long)e3.x * F4 + lane];
        acc.x = fmaf(w0, v0.x, acc.x); acc.y = fmaf(w0, v0.y, acc.y);
        acc.z = fmaf(w0, v0.z, acc.z); acc.w = fmaf(w0, v0.w, acc.w);
        acc.x = fmaf(w1, v1.x, acc.x); acc.y = fmaf(w1, v1.y, acc.y);
        acc.z = fmaf(w1, v1.z, acc.z); acc.w = fmaf(w1, v1.w, acc.w);
        acc.x = fmaf(w2, v2.x, acc.x); acc.y = fmaf(w2, v2.y, acc.y);
        acc.z = fmaf(w2, v2.z, acc.z); acc.w = fmaf(w2, v2.w, acc.w);
        acc.x = fmaf(w3, v3.x, acc.x); acc.y = fmaf(w3, v3.y, acc.y);
        acc.z = fmaf(w3, v3.z, acc.z); acc.w = fmaf(w3, v3.w, acc.w);
    }
    for (; i < end; i++) {
        int2 e0 = g_es[i];
        float w = __int_as_float(e0.y);
        float4 v = x4[(long)e0.x * F4 + lane];
        acc.x = fmaf(w, v.x, acc.x); acc.y = fmaf(w, v.y, acc.y);
        acc.z = fmaf(w, v.z, acc.z); acc.w = fmaf(w, v.w, acc.w);
    }
    ((float4*)g_y)[(long)d * F4 + lane] = f2tf4(acc);
}

// ---------------------------------------------------------------------------
__device__ __forceinline__ void mma_tf32(float c[4],
                                         unsigned a0, unsigned a1,
                                         unsigned a2, unsigned a3,
                                         unsigned b0, unsigned b1) {
    asm volatile(
        "mma.sync.aligned.m16n8k8.row.col.f32.tf32.tf32.f32 "
        "{%0,%1,%2,%3}, {%4,%5,%6,%7}, {%8,%9}, {%0,%1,%2,%3};"
        : "+f"(c[0]), "+f"(c[1]), "+f"(c[2]), "+f"(c[3])
        : "r"(a0), "r"(a1), "r"(a2), "r"(a3), "r"(b0), "r"(b1));
}

// ---------------------------------------------------------------------------
// Persistent fused tf32 tensor-core MLP — 148 CTAs x 512 threads, 1 CTA/SM.
// W1 AND W2 resident for the whole kernel; 128-row tiles (nt=8 per warp).
// smem: ysm 128xPAD_Y (67.6KB) + 2x F xPAD_W (139.3KB) = ~207 KB.
__global__ void __launch_bounds__(512, 1)
gemm_tc(const float* __restrict__ b1, const float* __restrict__ b2,
        float4* __restrict__ out4, int N, int nTiles) {
    extern __shared__ float smem[];
    float* ysm  = smem;                         // TROW x PAD_Y
    float* w1sm = smem + TROW * PAD_Y;          // F x PAD_W
    float* w2sm = w1sm + F * PAD_W;             // F x PAD_W

    int tid  = threadIdx.x;
    int lane = tid & 31;
    int w    = tid >> 5;                  // 0..15
    int g    = lane >> 2;                 // 0..7
    int tig  = lane & 3;                  // 0..3
    int f0   = (w & 7) * 16;              // feature base
    int nb   = (w >> 3) * 64;             // node base (0 or 64)

    // ---- Stage W1 and W2 once ----
    for (int i = tid; i < F * F4; i += 512) {
        int k = i >> 5, c = i & 31;
        ((float4*)(w1sm + k * PAD_W))[c] = ((const float4*)g_w1t)[i];
        ((float4*)(w2sm + k * PAD_W))[c] = ((const float4*)g_w2t)[i];
    }

    // Hoisted biases
    float bl1 = b1[f0 + g], bh1 = b1[f0 + g + 8];
    float bl2 = b2[f0 + g], bh2 = b2[f0 + g + 8];

    // BN partials accumulated across tiles in registers
    float csA[4] = {0.f, 0.f, 0.f, 0.f};
    float cqA[4] = {0.f, 0.f, 0.f, 0.f};
    int c4 = tid & 31;
    int ty = tid >> 5;                    // 0..15

    for (int tile = blockIdx.x; tile < nTiles; tile += gridDim.x) {
        int row0 = tile * TROW;

        __syncthreads();   // prior tile's ysm reads complete before overwrite
        for (int i = tid; i < TROW * F4; i += 512) {
            int r = i >> 5, c = i & 31;
            int gr = row0 + r;
            float4 v = (gr < N) ? ((const float4*)g_y)[(long)gr * F4 + c]
                                : make_float4(0.f, 0.f, 0.f, 0.f);
            ((float4*)(ysm + r * PAD_Y))[c] = v;
        }
        __syncthreads();

        // ---- GEMM1 (w1sm) + ReLU ----
        float acc[8][4];
        #pragma unroll
        for (int nt = 0; nt < 8; nt++) {
            acc[nt][0] = bl1; acc[nt][1] = bl1; acc[nt][2] = bh1; acc[nt][3] = bh1;
        }
        #pragma unroll
        for (int ks = 0; ks < 16; ks++) {
            int kb = ks * 8;
            unsigned a0 = __float_as_uint(w1sm[(kb + tig)     * PAD_W + f0 + g]);
            unsigned a1 = __float_as_uint(w1sm[(kb + tig)     * PAD_W + f0 + g + 8]);
            unsigned a2 = __float_as_uint(w1sm[(kb + tig + 4) * PAD_W + f0 + g]);
            unsigned a3 = __float_as_uint(w1sm[(kb + tig + 4) * PAD_W + f0 + g + 8]);
            #pragma unroll
            for (int nt = 0; nt < 8; nt++) {
                unsigned b0 = __float_as_uint(ysm[(nb + nt * 8 + g) * PAD_Y + kb + tig]);
                unsigned b1r = __float_as_uint(ysm[(nb + nt * 8 + g) * PAD_Y + kb + tig + 4]);
                mma_tf32(acc[nt], a0, a1, a2, a3, b0, b1r);
            }
        }
        #pragma unroll
        for (int nt = 0; nt < 8; nt++)
            #pragma unroll
            for (int j = 0; j < 4; j++)
                acc[nt][j] = fmaxf(acc[nt][j], 0.0f);

        __syncthreads();   // all reads of ysm done

        // ---- h1 (tf32) -> ysm ----
        #pragma unroll
        for (int nt = 0; nt < 8; nt++) {
            int r0r = (nb + nt * 8 + 2 * tig) * PAD_Y;
            int r1r = (nb + nt * 8 + 2 * tig + 1) * PAD_Y;
            ysm[r0r + f0 + g]     = __uint_as_float(f2tf(acc[nt][0]));
            ysm[r1r + f0 + g]     = __uint_as_float(f2tf(acc[nt][1]));
            ysm[r0r + f0 + g + 8] = __uint_as_float(f2tf(acc[nt][2]));
            ysm[r1r + f0 + g + 8] = __uint_as_float(f2tf(acc[nt][3]));
        }
        __syncthreads();

        // ---- GEMM2 (w2sm) ----
        #pragma unroll
        for (int nt = 0; nt < 8; nt++) {
            acc[nt][0] = bl2; acc[nt][1] = bl2; acc[nt][2] = bh2; acc[nt][3] = bh2;
        }
        #pragma unroll
        for (int ks = 0; ks < 16; ks++) {
            int kb = ks * 8;
            unsigned a0 = __float_as_uint(w2sm[(kb + tig)     * PAD_W + f0 + g]);
            unsigned a1 = __float_as_uint(w2sm[(kb + tig)     * PAD_W + f0 + g + 8]);
            unsigned a2 = __float_as_uint(w2sm[(kb + tig + 4) * PAD_W + f0 + g]);
            unsigned a3 = __float_as_uint(w2sm[(kb + tig + 4) * PAD_W + f0 + g + 8]);
            #pragma unroll
            for (int nt = 0; nt < 8; nt++) {
                unsigned b0 = __float_as_uint(ysm[(nb + nt * 8 + g) * PAD_Y + kb + tig]);
                unsigned b1r = __float_as_uint(ysm[(nb + nt * 8 + g) * PAD_Y + kb + tig + 4]);
                mma_tf32(acc[nt], a0, a1, a2, a3, b0, b1r);
            }
        }
        __syncthreads();   // all reads of ysm done

        // ---- h2 (fp32) -> ysm for coalesced store ----
        #pragma unroll
        for (int nt = 0; nt < 8; nt++) {
            int r0r = (nb + nt * 8 + 2 * tig) * PAD_Y;
            int r1r = (nb + nt * 8 + 2 * tig + 1) * PAD_Y;
            ysm[r0r + f0 + g]     = acc[nt][0];
            ysm[r1r + f0 + g]     = acc[nt][1];
            ysm[r0r + f0 + g + 8] = acc[nt][2];
            ysm[r1r + f0 + g + 8] = acc[nt][3];
        }
        __syncthreads();

        // ---- Coalesced store + BN partial accumulate ----
        #pragma unroll
        for (int j = 0; j < 8; j++) {
            int r = ty + j * 16;
            int gr = row0 + r;
            if (gr < N) {
                float4 v = ((const float4*)(ysm + r * PAD_Y))[c4];
                out4[(long)gr * F4 + c4] = v;
                csA[0] += v.x; csA[1] += v.y; csA[2] += v.z; csA[3] += v.w;
                cqA[0] += v.x * v.x; cqA[1] += v.y * v.y;
                cqA[2] += v.z * v.z; cqA[3] += v.w * v.w;
            }
        }
    }

    // ---- One BN reduction per CTA ----
    __syncthreads();
    #pragma unroll
    for (int j = 0; j < 4; j++) {
        ysm[ty * F + c4 * 4 + j]          = csA[j];
        ysm[16 * F + ty * F + c4 * 4 + j] = cqA[j];
    }
    __syncthreads();
    if (tid < F) {
        float s = 0.f, q = 0.f;
        #pragma unroll
        for (int t = 0; t < 16; t++) {
            s += ysm[t * F + tid];
            q += ysm[16 * F + t * F + tid];
        }
        atomicAdd(&g_sum[tid], s);
        atomicAdd(&g_sumsq[tid], q);
    }
}

// ---------------------------------------------------------------------------
__global__ void bn_k(float4* __restrict__ out4,
                     const float4* __restrict__ gamma4,
                     const float4* __restrict__ beta4, int N) {
    float invN = 1.0f / (float)N;
    for (int i = blockIdx.x * blockDim.x + threadIdx.x; i < N * F4;
         i += gridDim.x * blockDim.x) {
        int c = i & 31;
        float4 s = ((const float4*)g_sum)[c];
        float4 q = ((const float4*)g_sumsq)[c];
        float4 g = gamma4[c];
        float4 b = beta4[c];
        float4 v = out4[i];

        float m, var, is;
        m = s.x * invN; var = q.x * invN - m * m; is = rsqrtf(var + 1e-5f);
        v.x = (v.x - m) * is * g.x + b.x;
        m = s.y * invN; var = q.y * invN - m * m; is = rsqrtf(var + 1e-5f);
        v.y = (v.y - m) * is * g.y + b.y;
        m = s.z * invN; var = q.z * invN - m * m; is = rsqrtf(var + 1e-5f);
        v.z = (v.z - m) * is * g.z + b.z;
        m = s.w * invN; var = q.w * invN - m * m; is = rsqrtf(var + 1e-5f);
        v.w = (v.w - m) * is * g.w + b.w;

        out4[i] = v;
    }
}

// ---------------------------------------------------------------------------
extern "C" void kernel_launch(void* const* d_in, const int* in_sizes, int n_in,
                              void* d_out, int out_size) {
    const float* x     = (const float*)d_in[0];
    const float* ew    = (const float*)d_in[1];
    const float* W1    = (const float*)d_in[2];
    const float* b1    = (const float*)d_in[3];
    const float* W2    = (const float*)d_in[4];
    const float* b2    = (const float*)d_in[5];
    const float* eps   = (const float*)d_in[6];
    const float* gamma = (const float*)d_in[7];
    const float* beta  = (const float*)d_in[8];
    const int*   src   = (const int*)d_in[9];
    const int*   dst   = (const int*)d_in[10];

    int N = in_sizes[0] / F;
    int E = in_sizes[1];
    float* out = (float*)d_out;

    int smem_bytes = (TROW * PAD_Y + 2 * F * PAD_W) * (int)sizeof(float);
    cudaFuncSetAttribute(gemm_tc, cudaFuncAttributeMaxDynamicSharedMemorySize,
                         smem_bytes);

    int B1 = (N + 1023) / 1024;

    setup_k<<<(N + 255) / 256, 256>>>((const float4*)W1, (const float4*)W2, N);
    hist_k<<<1184, 256>>>(dst, E);
    scan1_k<<<B1, 1024>>>(N);
    scan3_k<<<(N + 255) / 256, 256>>>(N, E, B1);
    place_k<<<1184, 256>>>(src, dst, ew, E);
    gather_k<<<(N * 32 + 255) / 256, 256>>>((const float4*)x, eps, N);

    int nTiles = (N + TROW - 1) / TROW;
    gemm_tc<<<GCTAS, 512, smem_bytes>>>(b1, b2, (float4*)out, N, nTiles);

    bn_k<<<1184, 256>>>((float4*)out, (const float4*)gamma,
                        (const float4*)beta, N);
}

// round 16
// speedup vs baseline: 1.9981x; 1.0538x over previous
#include <cuda_runtime.h>

#define F     128
#define F4    32
#define NMAX  50000
#define EMAX  800000
#define TROW  128         // node rows per gemm tile
#define PAD_Y 132         // ysm row pad: B-frag (4g+tig) + transpose stores conflict-free
#define PAD_W 136         // wsm row pad: A-frag (8tig+g) conflict-free
#define GCTAS 148         // persistent gemm CTAs (1/SM)

// Scratch (allocation-free rule: __device__ globals; .bss zero-initialized)
__device__ __align__(16) float g_y[NMAX * F];      // tf32-rounded aggregated feats
__device__ __align__(16) float g_w1t[F * F];       // tf32-rounded W1
__device__ __align__(16) float g_w2t[F * F];       // tf32-rounded W2
__device__ __align__(16) float g_sum[F];
__device__ __align__(16) float g_sumsq[F];
__device__ __align__(16) int g_cnt[NMAX];          // histogram, then cursor (re-zeroed by bn_k)
__device__ int   g_offs[NMAX + 1];                 // segment offsets
__device__ int   g_bsum[64];                       // scan block sums
__device__ __align__(16) int2 g_es[EMAX];          // dst-sorted (src, w) pairs

// ---------------------------------------------------------------------------
__device__ __forceinline__ unsigned f2tf(float f) {
    unsigned u;
    asm("cvt.rna.tf32.f32 %0, %1;" : "=r"(u) : "f"(f));
    return u;
}
__device__ __forceinline__ float4 f2tf4(float4 v) {
    return make_float4(__uint_as_float(f2tf(v.x)), __uint_as_float(f2tf(v.y)),
                       __uint_as_float(f2tf(v.z)), __uint_as_float(f2tf(v.w)));
}

// hist + one-time W tf32 conversion + BN-stat zeroing (all pre-consumers)
__global__ void hist_k(const int* __restrict__ dst,
                       const float4* __restrict__ W1,
                       const float4* __restrict__ W2, int E) {
    int i = blockIdx.x * blockDim.x + threadIdx.x;
    if (i < F * F4) {
        ((float4*)g_w1t)[i] = f2tf4(W1[i]);
        ((float4*)g_w2t)[i] = f2tf4(W2[i]);
    }
    if (i < F) { g_sum[i] = 0.0f; g_sumsq[i] = 0.0f; }
    for (int e = i; e < E; e += gridDim.x * blockDim.x)
        atomicAdd(&g_cnt[dst[e]], 1);
}

// Coalesced block-local exclusive scan (1024/block)
__global__ void scan1_k(int N) {
    __shared__ int sh[1024];
    int t = threadIdx.x;
    int i = blockIdx.x * 1024 + t;
    int c = (i < N) ? g_cnt[i] : 0;
    sh[t] = c;
    __syncthreads();
    #pragma unroll
    for (int off = 1; off < 1024; off <<= 1) {
        int v = (t >= off) ? sh[t - off] : 0;
        __syncthreads();
        sh[t] += v;
        __syncthreads();
    }
    if (i < N) g_offs[i] = sh[t] - c;     // exclusive, block-local
    if (t == 1023) g_bsum[blockIdx.x] = sh[1023];
}

// Fixup: each block scans the <=64 block sums in smem, then applies prefix.
__global__ void scan3_k(int N, int E, int B1) {
    __shared__ int bs[64];
    int t = threadIdx.x;
    if (t < 64) bs[t] = (t < B1) ? g_bsum[t] : 0;
    __syncthreads();
    #pragma unroll
    for (int off = 1; off < 64; off <<= 1) {
        int v = 0;
        if (t < 64 && t >= off) v = bs[t - off];
        __syncthreads();
        if (t < 64) bs[t] += v;           // inclusive scan
        __syncthreads();
    }
    int i = blockIdx.x * blockDim.x + t;
    if (i < N) {
        int k = i >> 10;
        int pre = (k == 0) ? 0 : bs[k - 1];
        int o = g_offs[i] + pre;
        g_offs[i] = o;
        g_cnt[i]  = o;                    // cursor for placement
    }
    if (i == 0) g_offs[N] = E;
}

// Counting-sort placement: one 8B store per edge (src, weight packed)
__global__ void place_k(const int* __restrict__ src,
                        const int* __restrict__ dst,
                        const float* __restrict__ ew, int E) {
    for (int e = blockIdx.x * blockDim.x + threadIdx.x; e < E;
         e += gridDim.x * blockDim.x) {
        int idx = atomicAdd(&g_cnt[dst[e]], 1);
        g_es[idx] = make_int2(src[e], __float_as_int(ew[e]));
    }
}

// Segmented gather-reduce: one warp per dst node. Stores tf32-ROUNDED bits.
__global__ void gather_k(const float4* __restrict__ x4,
                         const float* __restrict__ eps, int N) {
    int gt = blockIdx.x * blockDim.x + threadIdx.x;
    int d = gt >> 5;
    if (d >= N) return;
    int lane = gt & 31;

    float s1 = 1.0f + eps[0];
    float4 acc = x4[(long)d * F4 + lane];
    acc.x *= s1; acc.y *= s1; acc.z *= s1; acc.w *= s1;

    int i   = g_offs[d];
    int end = g_offs[d + 1];

    for (; i + 4 <= end; i += 4) {
        int2 e0 = g_es[i],     e1 = g_es[i + 1];
        int2 e2 = g_es[i + 2], e3 = g_es[i + 3];
        float w0 = __int_as_float(e0.y), w1 = __int_as_float(e1.y);
        float w2 = __int_as_float(e2.y), w3 = __int_as_float(e3.y);
        float4 v0 = x4[(long)e0.x * F4 + lane];
        float4 v1 = x4[(long)e1.x * F4 + lane];
        float4 v2 = x4[(long)e2.x * F4 + lane];
        float4 v3 = x4[(long)e3.x * F4 + lane];
        acc.x = fmaf(w0, v0.x, acc.x); acc.y = fmaf(w0, v0.y, acc.y);
        acc.z = fmaf(w0, v0.z, acc.z); acc.w = fmaf(w0, v0.w, acc.w);
        acc.x = fmaf(w1, v1.x, acc.x); acc.y = fmaf(w1, v1.y, acc.y);
        acc.z = fmaf(w1, v1.z, acc.z); acc.w = fmaf(w1, v1.w, acc.w);
        acc.x = fmaf(w2, v2.x, acc.x); acc.y = fmaf(w2, v2.y, acc.y);
        acc.z = fmaf(w2, v2.z, acc.z); acc.w = fmaf(w2, v2.w, acc.w);
        acc.x = fmaf(w3, v3.x, acc.x); acc.y = fmaf(w3, v3.y, acc.y);
        acc.z = fmaf(w3, v3.z, acc.z); acc.w = fmaf(w3, v3.w, acc.w);
    }
    for (; i < end; i++) {
        int2 e0 = g_es[i];
        float w = __int_as_float(e0.y);
        float4 v = x4[(long)e0.x * F4 + lane];
        acc.x = fmaf(w, v.x, acc.x); acc.y = fmaf(w, v.y, acc.y);
        acc.z = fmaf(w, v.z, acc.z); acc.w = fmaf(w, v.w, acc.w);
    }
    ((float4*)g_y)[(long)d * F4 + lane] = f2tf4(acc);
}

// ---------------------------------------------------------------------------
__device__ __forceinline__ void mma_tf32(float c[4],
                                         unsigned a0, unsigned a1,
                                         unsigned a2, unsigned a3,
                                         unsigned b0, unsigned b1) {
    asm volatile(
        "mma.sync.aligned.m16n8k8.row.col.f32.tf32.tf32.f32 "
        "{%0,%1,%2,%3}, {%4,%5,%6,%7}, {%8,%9}, {%0,%1,%2,%3};"
        : "+f"(c[0]), "+f"(c[1]), "+f"(c[2]), "+f"(c[3])
        : "r"(a0), "r"(a1), "r"(a2), "r"(a3), "r"(b0), "r"(b1));
}

// ---------------------------------------------------------------------------
// Persistent fused tf32 tensor-core MLP — 148 CTAs x 512 threads, 1 CTA/SM.
// Warp tile rebalanced to 32 features x 32 rows (4x4 warp grid):
// smem redundancy B: 4x, A: 4x (was 8x/2x) -> 20% fewer LDS in mma loop.
__global__ void __launch_bounds__(512, 1)
gemm_tc(const float* __restrict__ b1, const float* __restrict__ b2,
        float4* __restrict__ out4, int N, int nTiles) {
    extern __shared__ float smem[];
    float* ysm  = smem;                         // TROW x PAD_Y
    float* w1sm = smem + TROW * PAD_Y;          // F x PAD_W
    float* w2sm = w1sm + F * PAD_W;             // F x PAD_W

    int tid  = threadIdx.x;
    int lane = tid & 31;
    int w    = tid >> 5;                  // 0..15
    int g    = lane >> 2;                 // 0..7
    int tig  = lane & 3;                  // 0..3
    int f0   = (w & 3) * 32;              // feature base (32 feats/warp)
    int nb   = (w >> 2) * 32;             // node base (32 rows/warp)

    // ---- Stage W1 and W2 once ----
    for (int i = tid; i < F * F4; i += 512) {
        int k = i >> 5, c = i & 31;
        ((float4*)(w1sm + k * PAD_W))[c] = ((const float4*)g_w1t)[i];
        ((float4*)(w2sm + k * PAD_W))[c] = ((const float4*)g_w2t)[i];
    }

    // Hoisted biases: per m-half mt, features f0+16mt+g and +8
    float bl1[2], bh1[2], bl2[2], bh2[2];
    #pragma unroll
    for (int mt = 0; mt < 2; mt++) {
        bl1[mt] = b1[f0 + 16 * mt + g];  bh1[mt] = b1[f0 + 16 * mt + 8 + g];
        bl2[mt] = b2[f0 + 16 * mt + g];  bh2[mt] = b2[f0 + 16 * mt + 8 + g];
    }

    // BN partials accumulated across tiles in registers
    float csA[4] = {0.f, 0.f, 0.f, 0.f};
    float cqA[4] = {0.f, 0.f, 0.f, 0.f};
    int c4 = tid & 31;
    int ty = tid >> 5;                    // 0..15

    for (int tile = blockIdx.x; tile < nTiles; tile += gridDim.x) {
        int row0 = tile * TROW;

        __syncthreads();   // prior tile's ysm reads complete before overwrite
        for (int i = tid; i < TROW * F4; i += 512) {
            int r = i >> 5, c = i & 31;
            int gr = row0 + r;
            float4 v = (gr < N) ? ((const float4*)g_y)[(long)gr * F4 + c]
                                : make_float4(0.f, 0.f, 0.f, 0.f);
            ((float4*)(ysm + r * PAD_Y))[c] = v;
        }
        __syncthreads();

        // ---- GEMM1 (w1sm) + ReLU ----
        float acc[4][2][4];
        #pragma unroll
        for (int nt = 0; nt < 4; nt++)
            #pragma unroll
            for (int mt = 0; mt < 2; mt++) {
                acc[nt][mt][0] = bl1[mt]; acc[nt][mt][1] = bl1[mt];
                acc[nt][mt][2] = bh1[mt]; acc[nt][mt][3] = bh1[mt];
            }
        #pragma unroll
        for (int ks = 0; ks < 16; ks++) {
            int kb = ks * 8;
            unsigned a[2][4];
            #pragma unroll
            for (int mt = 0; mt < 2; mt++) {
                int fb = f0 + 16 * mt + g;
                a[mt][0] = __float_as_uint(w1sm[(kb + tig)     * PAD_W + fb]);
                a[mt][1] = __float_as_uint(w1sm[(kb + tig)     * PAD_W + fb + 8]);
                a[mt][2] = __float_as_uint(w1sm[(kb + tig + 4) * PAD_W + fb]);
                a[mt][3] = __float_as_uint(w1sm[(kb + tig + 4) * PAD_W + fb + 8]);
            }
            #pragma unroll
            for (int nt = 0; nt < 4; nt++) {
                unsigned b0 = __float_as_uint(ysm[(nb + nt * 8 + g) * PAD_Y + kb + tig]);
                unsigned b1r = __float_as_uint(ysm[(nb + nt * 8 + g) * PAD_Y + kb + tig + 4]);
                #pragma unroll
                for (int mt = 0; mt < 2; mt++)
                    mma_tf32(acc[nt][mt], a[mt][0], a[mt][1], a[mt][2], a[mt][3], b0, b1r);
            }
        }
        #pragma unroll
        for (int nt = 0; nt < 4; nt++)
            #pragma unroll
            for (int mt = 0; mt < 2; mt++)
                #pragma unroll
                for (int j = 0; j < 4; j++)
                    acc[nt][mt][j] = fmaxf(acc[nt][mt][j], 0.0f);

        __syncthreads();   // all reads of ysm done

        // ---- h1 (tf32) -> ysm transposed ----
        #pragma unroll
        for (int nt = 0; nt < 4; nt++) {
            int r0r = (nb + nt * 8 + 2 * tig) * PAD_Y;
            int r1r = r0r + PAD_Y;
            #pragma unroll
            for (int mt = 0; mt < 2; mt++) {
                int col = f0 + 16 * mt + g;
                ysm[r0r + col]     = __uint_as_float(f2tf(acc[nt][mt][0]));
                ysm[r1r + col]     = __uint_as_float(f2tf(acc[nt][mt][1]));
                ysm[r0r + col + 8] = __uint_as_float(f2tf(acc[nt][mt][2]));
                ysm[r1r + col + 8] = __uint_as_float(f2tf(acc[nt][mt][3]));
            }
        }
        __syncthreads();

        // ---- GEMM2 (w2sm) ----
        #pragma unroll
        for (int nt = 0; nt < 4; nt++)
            #pragma unroll
            for (int mt = 0; mt < 2; mt++) {
                acc[nt][mt][0] = bl2[mt]; acc[nt][mt][1] = bl2[mt];
                acc[nt][mt][2] = bh2[mt]; acc[nt][mt][3] = bh2[mt];
            }
        #pragma unroll
        for (int ks = 0; ks < 16; ks++) {
            int kb = ks * 8;
            unsigned a[2][4];
            #pragma unroll
            for (int mt = 0; mt < 2; mt++) {
                int fb = f0 + 16 * mt + g;
                a[mt][0] = __float_as_uint(w2sm[(kb + tig)     * PAD_W + fb]);
                a[mt][1] = __float_as_uint(w2sm[(kb + tig)     * PAD_W + fb + 8]);
                a[mt][2] = __float_as_uint(w2sm[(kb + tig + 4) * PAD_W + fb]);
                a[mt][3] = __float_as_uint(w2sm[(kb + tig + 4) * PAD_W + fb + 8]);
            }
            #pragma unroll
            for (int nt = 0; nt < 4; nt++) {
                unsigned b0 = __float_as_uint(ysm[(nb + nt * 8 + g) * PAD_Y + kb + tig]);
                unsigned b1r = __float_as_uint(ysm[(nb + nt * 8 + g) * PAD_Y + kb + tig + 4]);
                #pragma unroll
                for (int mt = 0; mt < 2; mt++)
                    mma_tf32(acc[nt][mt], a[mt][0], a[mt][1], a[mt][2], a[mt][3], b0, b1r);
            }
        }
        __syncthreads();   // all reads of ysm done

        // ---- h2 (fp32) -> ysm transposed for coalesced store ----
        #pragma unroll
        for (int nt = 0; nt < 4; nt++) {
            int r0r = (nb + nt * 8 + 2 * tig) * PAD_Y;
            int r1r = r0r + PAD_Y;
            #pragma unroll
            for (int mt = 0; mt < 2; mt++) {
                int col = f0 + 16 * mt + g;
                ysm[r0r + col]     = acc[nt][mt][0];
                ysm[r1r + col]     = acc[nt][mt][1];
                ysm[r0r + col + 8] = acc[nt][mt][2];
                ysm[r1r + col + 8] = acc[nt][mt][3];
            }
        }
        __syncthreads();

        // ---- Coalesced store + BN partial accumulate ----
        #pragma unroll
        for (int j = 0; j < 8; j++) {
            int r = ty + j * 16;
            int gr = row0 + r;
            if (gr < N) {
                float4 v = ((const float4*)(ysm + r * PAD_Y))[c4];
                out4[(long)gr * F4 + c4] = v;
                csA[0] += v.x; csA[1] += v.y; csA[2] += v.z; csA[3] += v.w;
                cqA[0] += v.x * v.x; cqA[1] += v.y * v.y;
                cqA[2] += v.z * v.z; cqA[3] += v.w * v.w;
            }
        }
    }

    // ---- One BN reduction per CTA ----
    __syncthreads();
    #pragma unroll
    for (int j = 0; j < 4; j++) {
        ysm[ty * F + c4 * 4 + j]          = csA[j];
        ysm[16 * F + ty * F + c4 * 4 + j] = cqA[j];
    }
    __syncthreads();
    if (tid < F) {
        float s = 0.f, q = 0.f;
        #pragma unroll
        for (int t = 0; t < 16; t++) {
            s += ysm[t * F + tid];
            q += ysm[16 * F + t * F + tid];
        }
        atomicAdd(&g_sum[tid], s);
        atomicAdd(&g_sumsq[tid], q);
    }
}

// ---------------------------------------------------------------------------
// BN normalize; also re-zeroes g_cnt for the NEXT invocation (g_cnt unused here).
__global__ void bn_k(float4* __restrict__ out4,
                     const float4* __restrict__ gamma4,
                     const float4* __restrict__ beta4, int N) {
    float invN = 1.0f / (float)N;
    int stride = gridDim.x * blockDim.x;
    for (int i = blockIdx.x * blockDim.x + threadIdx.x; i < N * F4; i += stride) {
        int c = i & 31;
        float4 s = ((const float4*)g_sum)[c];
        float4 q = ((const float4*)g_sumsq)[c];
        float4 g = gamma4[c];
        float4 b = beta4[c];
        float4 v = out4[i];

        float m, var, is;
        m = s.x * invN; var = q.x * invN - m * m; is = rsqrtf(var + 1e-5f);
        v.x = (v.x - m) * is * g.x + b.x;
        m = s.y * invN; var = q.y * invN - m * m; is = rsqrtf(var + 1e-5f);
        v.y = (v.y - m) * is * g.y + b.y;
        m = s.z * invN; var = q.z * invN - m * m; is = rsqrtf(var + 1e-5f);
        v.z = (v.z - m) * is * g.z + b.z;
        m = s.w * invN; var = q.w * invN - m * m; is = rsqrtf(var + 1e-5f);
        v.w = (v.w - m) * is * g.w + b.w;

        out4[i] = v;
    }
    // zero histogram counters for the next replay (NMAX % 4 == 0)
    int4 z = make_int4(0, 0, 0, 0);
    for (int i = blockIdx.x * blockDim.x + threadIdx.x; i < NMAX / 4; i += stride)
        ((int4*)g_cnt)[i] = z;
}

// ---------------------------------------------------------------------------
extern "C" void kernel_launch(void* const* d_in, const int* in_sizes, int n_in,
                              void* d_out, int out_size) {
    const float* x     = (const float*)d_in[0];
    const float* ew    = (const float*)d_in[1];
    const float* W1    = (const float*)d_in[2];
    const float* b1    = (const float*)d_in[3];
    const float* W2    = (const float*)d_in[4];
    const float* b2    = (const float*)d_in[5];
    const float* eps   = (const float*)d_in[6];
    const float* gamma = (const float*)d_in[7];
    const float* beta  = (const float*)d_in[8];
    const int*   src   = (const int*)d_in[9];
    const int*   dst   = (const int*)d_in[10];

    int N = in_sizes[0] / F;
    int E = in_sizes[1];
    float* out = (float*)d_out;

    int smem_bytes = (TROW * PAD_Y + 2 * F * PAD_W) * (int)sizeof(float);
    cudaFuncSetAttribute(gemm_tc, cudaFuncAttributeMaxDynamicSharedMemorySize,
                         smem_bytes);

    int B1 = (N + 1023) / 1024;

    hist_k<<<1184, 256>>>(dst, (const float4*)W1, (const float4*)W2, E);
    scan1_k<<<B1, 1024>>>(N);
    scan3_k<<<(N + 255) / 256, 256>>>(N, E, B1);
    place_k<<<1184, 256>>>(src, dst, ew, E);
    gather_k<<<(N * 32 + 255) / 256, 256>>>((const float4*)x, eps, N);

    int nTiles = (N + TROW - 1) / TROW;
    gemm_tc<<<GCTAS, 512, smem_bytes>>>(b1, b2, (float4*)out, N, nTiles);

    bn_k<<<1184, 256>>>((float4*)out, (const float4*)gamma,
                        (const float4*)beta, N);
}